// round 1
// baseline (speedup 1.0000x reference)
#include <cuda_runtime.h>
#include <cstdint>

// ---------------- problem constants ----------------
#define N_RNA   2000
#define N_PROT  1512
#define NT      3512        // N_RNA + N_PROT
#define SZ_R    3000
#define FUN_IN  5603
#define H_ATT   2048
#define H_FUN   4096
#define DCOLS   512         // ATT(256) + FUN(256)
#define BATCH   8192
#define PROTEIN 1512
#define FLATSZ  8192        // 32*2*128

// scratch: hidden activations, reused by both MLP branches (57.5 MB)
__device__ float g_hidden[NT * (size_t)H_FUN];

// ---------------- big GEMM: C = gelu(A @ B + bias), A = concat(A0,A1) rows ----
__global__ __launch_bounds__(256)
void gemm_gelu(const float* __restrict__ A0, const float* __restrict__ A1,
               int splitRow, int M, int N, int K, int lda,
               const float* __restrict__ B, const float* __restrict__ bias,
               float* __restrict__ C)
{
    __shared__ __align__(16) float As[8][128];
    __shared__ __align__(16) float Bs[8][128];
    int tid = threadIdx.x;
    int tx = tid & 15, ty = tid >> 4;
    int rowBase = blockIdx.y * 128;
    int colBase = blockIdx.x * 128;
    float acc[8][8] = {};

    for (int k0 = 0; k0 < K; k0 += 8) {
        #pragma unroll
        for (int i = 0; i < 4; i++) {
            int lin = tid + i * 256;
            int kk = lin & 7, m = lin >> 3;
            int gr = rowBase + m, gk = k0 + kk;
            float v = 0.f;
            if (gr < M && gk < K) {
                const float* Ar = (gr < splitRow) ? (A0 + (size_t)gr * lda)
                                                  : (A1 + (size_t)(gr - splitRow) * lda);
                v = Ar[gk];
            }
            As[kk][m] = v;
        }
        #pragma unroll
        for (int i = 0; i < 4; i++) {
            int lin = tid + i * 256;
            int kk = lin >> 7, n = lin & 127;
            int gk = k0 + kk, gc = colBase + n;
            Bs[kk][n] = (gk < K && gc < N) ? B[(size_t)gk * N + gc] : 0.f;
        }
        __syncthreads();
        #pragma unroll
        for (int kk = 0; kk < 8; kk++) {
            float4 a0 = *(const float4*)&As[kk][ty * 8];
            float4 a1 = *(const float4*)&As[kk][ty * 8 + 4];
            float4 b0 = *(const float4*)&Bs[kk][tx * 8];
            float4 b1 = *(const float4*)&Bs[kk][tx * 8 + 4];
            float av[8] = {a0.x,a0.y,a0.z,a0.w,a1.x,a1.y,a1.z,a1.w};
            float bv[8] = {b0.x,b0.y,b0.z,b0.w,b1.x,b1.y,b1.z,b1.w};
            #pragma unroll
            for (int i = 0; i < 8; i++)
                #pragma unroll
                for (int j = 0; j < 8; j++)
                    acc[i][j] += av[i] * bv[j];
        }
        __syncthreads();
    }
    #pragma unroll
    for (int i = 0; i < 8; i++) {
        int r = rowBase + ty * 8 + i;
        if (r >= M) continue;
        #pragma unroll
        for (int j = 0; j < 8; j++) {
            int c = colBase + tx * 8 + j;
            if (c >= N) continue;
            float v = acc[i][j] + bias[c];
            v = 0.5f * v * (1.0f + erff(v * 0.70710678118654752f));   // exact gelu
            C[(size_t)r * N + c] = v;
        }
    }
}

// ---------------- small GEMM: e[:, colOff:colOff+N] = sigmoid(A @ B + bias) ----
__global__ __launch_bounds__(256)
void gemm_sigmoid(const float* __restrict__ A, int M, int N, int K, int lda,
                  const float* __restrict__ B, const float* __restrict__ bias,
                  float* __restrict__ E, int colOff)
{
    __shared__ __align__(16) float As[16][64];
    __shared__ __align__(16) float Bs[16][64];
    int tid = threadIdx.x;
    int tx = tid & 15, ty = tid >> 4;
    int rowBase = blockIdx.y * 64;
    int colBase = blockIdx.x * 64;
    float acc[4][4] = {};

    for (int k0 = 0; k0 < K; k0 += 16) {
        #pragma unroll
        for (int i = 0; i < 4; i++) {
            int lin = tid + i * 256;
            int kk = lin & 15, m = lin >> 4;
            int gr = rowBase + m, gk = k0 + kk;
            As[kk][m] = (gr < M && gk < K) ? A[(size_t)gr * lda + gk] : 0.f;
        }
        #pragma unroll
        for (int i = 0; i < 4; i++) {
            int lin = tid + i * 256;
            int kk = lin >> 6, n = lin & 63;
            int gk = k0 + kk, gc = colBase + n;
            Bs[kk][n] = (gk < K && gc < N) ? B[(size_t)gk * N + gc] : 0.f;
        }
        __syncthreads();
        #pragma unroll
        for (int kk = 0; kk < 16; kk++) {
            float4 a = *(const float4*)&As[kk][ty * 4];
            float4 b = *(const float4*)&Bs[kk][tx * 4];
            float av[4] = {a.x,a.y,a.z,a.w};
            float bv[4] = {b.x,b.y,b.z,b.w};
            #pragma unroll
            for (int i = 0; i < 4; i++)
                #pragma unroll
                for (int j = 0; j < 4; j++)
                    acc[i][j] += av[i] * bv[j];
        }
        __syncthreads();
    }
    #pragma unroll
    for (int i = 0; i < 4; i++) {
        int r = rowBase + ty * 4 + i;
        if (r >= M) continue;
        #pragma unroll
        for (int j = 0; j < 4; j++) {
            int c = colBase + tx * 4 + j;
            if (c >= N) continue;
            float v = acc[i][j] + bias[c];
            v = 1.0f / (1.0f + __expf(-v));
            E[(size_t)r * DCOLS + colOff + c] = v;
        }
    }
}

// ---------------- fused gather + conv1/avgpool + conv2/maxpool + tanh + out GEMM
// one CTA (256 thr) per batch item
__global__ __launch_bounds__(256)
void conv_fused(const float* __restrict__ e, const int* __restrict__ idx,
                const float* __restrict__ w1, const float* __restrict__ b1,
                const float* __restrict__ w2, const float* __restrict__ b2,
                const float* __restrict__ Wout, const float* __restrict__ bout,
                float* __restrict__ outP, float* __restrict__ flatP)
{
    extern __shared__ float sm[];
    float* xs  = sm;             // 2 * 516   (input with +-2 halo)
    float* p1s = xs + 1032;      // 16 * 2 * 260 (pooled conv1, +-2 halo)
    float* w1s = p1s + 8320;     // 240
    float* b1s = w1s + 240;      // 16
    float* w2s = b1s + 16;       // 7680
    float* b2s = w2s + 7680;     // 32   -> total 17320 floats = 69280 B
    __shared__ float redsum[8][2];

    int t = threadIdx.x;
    int b = blockIdx.x;

    for (int i = t; i < 240; i += 256)  w1s[i] = w1[i];
    for (int i = t; i < 7680; i += 256) w2s[i] = w2[i];
    if (t < 16) b1s[t] = b1[t];
    if (t < 32) b2s[t] = b2[t];

    int id  = idx[b];
    int rno = id / PROTEIN;
    int pno = id - rno * PROTEIN;
    const float* row0 = e + (size_t)rno * DCOLS;
    const float* row1 = e + (size_t)(N_RNA + pno) * DCOLS;
    for (int i = t; i < 1032; i += 256) {
        int rr = (i >= 516), c = i - rr * 516;
        float v = 0.f;
        if (c >= 2 && c < 514) v = (rr == 0 ? row0 : row1)[c - 2];
        xs[i] = v;
    }
    if (t < 128) {   // zero p1 halo columns (0,1,258,259 of each of 32 rows)
        int rr = t >> 2, j = t & 3;
        int col = (j < 2) ? j : 256 + j;
        p1s[rr * 260 + col] = 0.f;
    }
    __syncthreads();

    // conv1 (3x5, pad2) + leaky + 2x2 avgpool -> p1s[16][2][256]
    for (int li = t; li < 8192; li += 256) {
        int c = li >> 9, ph = (li >> 8) & 1, pw = li & 255;
        const float* wc = &w1s[c * 15];
        float bb = b1s[c];
        float s = 0.f;
        #pragma unroll
        for (int d = 0; d < 4; d++) {
            int h = 2 * ph + (d >> 1);
            int w = 2 * pw + (d & 1);
            float acc = bb;
            #pragma unroll
            for (int kh = 0; kh < 3; kh++) {
                int r = h + kh - 2;
                if (r >= 0 && r < 2) {
                    #pragma unroll
                    for (int kw = 0; kw < 5; kw++)
                        acc += wc[kh * 5 + kw] * xs[r * 516 + w + kw];
                }
            }
            s += (acc >= 0.f) ? acc : 0.01f * acc;
        }
        p1s[(c * 2 + ph) * 260 + pw + 2] = 0.25f * s;
    }
    __syncthreads();

    // conv2 (16in,3x5,pad2) + leaky + 2x2 maxpool + tanh; thread = (ph,pw) pair
    int ph = t >> 7;           // uniform per warp
    int pw = t & 127;
    float o0 = 0.f, o1 = 0.f;
    for (int c = 0; c < 32; c++) {
        float bb = b2s[c];
        float a0 = bb, a1 = bb, a2 = bb, a3 = bb;
        const float* wc = &w2s[c * 240];
        #pragma unroll 4
        for (int ci = 0; ci < 16; ci++) {
            const float2* q0 = (const float2*)&p1s[(ci * 2 + 0) * 260 + 2 * pw];
            const float2* q1 = (const float2*)&p1s[(ci * 2 + 1) * 260 + 2 * pw];
            float2 u0 = q0[0], u1 = q0[1], u2 = q0[2];
            float2 v0 = q1[0], v1 = q1[1], v2 = q1[2];
            float r0[6] = {u0.x,u0.y,u1.x,u1.y,u2.x,u2.y};
            float r1[6] = {v0.x,v0.y,v1.x,v1.y,v2.x,v2.y};
            const float* w = wc + ci * 15;
            if (ph == 0) {
                // a0,a1 = conv h=0 (kh=2 -> row0); a2,a3 = h=1 (kh=1 -> row0, kh=2 -> row1)
                #pragma unroll
                for (int kw = 0; kw < 5; kw++) {
                    float wA = w[10 + kw], wB = w[5 + kw];
                    a0 += wA * r0[kw];
                    a1 += wA * r0[kw + 1];
                    a2 += wB * r0[kw]     + wA * r1[kw];
                    a3 += wB * r0[kw + 1] + wA * r1[kw + 1];
                }
            } else {
                // a0,a1 = h=2 (kh=0 -> row0, kh=1 -> row1); a2,a3 = h=3 (kh=0 -> row1)
                #pragma unroll
                for (int kw = 0; kw < 5; kw++) {
                    float wA = w[kw], wB = w[5 + kw];
                    a0 += wA * r0[kw]     + wB * r1[kw];
                    a1 += wA * r0[kw + 1] + wB * r1[kw + 1];
                    a2 += wA * r1[kw];
                    a3 += wA * r1[kw + 1];
                }
            }
        }
        a0 = (a0 >= 0.f) ? a0 : 0.01f * a0;
        a1 = (a1 >= 0.f) ? a1 : 0.01f * a1;
        a2 = (a2 >= 0.f) ? a2 : 0.01f * a2;
        a3 = (a3 >= 0.f) ? a3 : 0.01f * a3;
        float m  = fmaxf(fmaxf(a0, a1), fmaxf(a2, a3));
        float tv = tanhf(m);
        int fi = c * 256 + ph * 128 + pw;
        flatP[(size_t)b * FLATSZ + fi] = tv;
        o0 += tv * Wout[2 * fi];
        o1 += tv * Wout[2 * fi + 1];
    }

    // deterministic block reduction for the 2-wide output GEMM
    #pragma unroll
    for (int off = 16; off > 0; off >>= 1) {
        o0 += __shfl_down_sync(0xffffffffu, o0, off);
        o1 += __shfl_down_sync(0xffffffffu, o1, off);
    }
    if ((t & 31) == 0) { redsum[t >> 5][0] = o0; redsum[t >> 5][1] = o1; }
    __syncthreads();
    if (t == 0) {
        float s0 = 0.f, s1 = 0.f;
        #pragma unroll
        for (int w = 0; w < 8; w++) { s0 += redsum[w][0]; s1 += redsum[w][1]; }
        outP[2 * b]     = s0 + bout[0];
        outP[2 * b + 1] = s1 + bout[1];
    }
}

// ---------------- launch ----------------
extern "C" void kernel_launch(void* const* d_in, const int* in_sizes, int n_in,
                              void* d_out, int out_size)
{
    (void)in_sizes; (void)n_in; (void)out_size;
    const float* r_att   = (const float*)d_in[0];
    const float* p_att   = (const float*)d_in[1];
    const float* r_fun   = (const float*)d_in[2];
    const float* p_fun   = (const float*)d_in[3];
    const int*   idx     = (const int*)  d_in[4];
    const float* W_att1  = (const float*)d_in[5];
    const float* b_att1  = (const float*)d_in[6];
    const float* W_att2  = (const float*)d_in[7];
    const float* b_att2  = (const float*)d_in[8];
    const float* W_fun1  = (const float*)d_in[9];
    const float* b_fun1  = (const float*)d_in[10];
    const float* W_fun2  = (const float*)d_in[11];
    const float* b_fun2  = (const float*)d_in[12];
    const float* conv1_w = (const float*)d_in[13];
    const float* conv1_b = (const float*)d_in[14];
    const float* conv2_w = (const float*)d_in[15];
    const float* conv2_b = (const float*)d_in[16];
    const float* W_out   = (const float*)d_in[17];
    const float* b_out   = (const float*)d_in[18];

    float* out   = (float*)d_out;
    float* e     = out;                              // [3512, 512] = e_r ++ e_p
    float* outP  = out + (size_t)NT * DCOLS;         // [8192, 2]
    float* flatP = outP + 2 * BATCH;                 // [8192, 8192]

    float* hidden = nullptr;
    cudaGetSymbolAddress((void**)&hidden, g_hidden);

    // ATT branch
    gemm_gelu<<<dim3(H_ATT / 128, (NT + 127) / 128), 256>>>(
        r_att, p_att, N_RNA, NT, H_ATT, SZ_R, SZ_R, W_att1, b_att1, hidden);
    gemm_sigmoid<<<dim3(256 / 64, (NT + 63) / 64), 256>>>(
        hidden, NT, 256, H_ATT, H_ATT, W_att2, b_att2, e, 0);
    // FUN branch (reuses hidden scratch)
    gemm_gelu<<<dim3(H_FUN / 128, (NT + 127) / 128), 256>>>(
        r_fun, p_fun, N_RNA, NT, H_FUN, FUN_IN, FUN_IN, W_fun1, b_fun1, hidden);
    gemm_sigmoid<<<dim3(256 / 64, (NT + 63) / 64), 256>>>(
        hidden, NT, 256, H_FUN, H_FUN, W_fun2, b_fun2, e, 256);

    // fused conv stack
    const int smemB = 17320 * 4;
    cudaFuncSetAttribute(conv_fused, cudaFuncAttributeMaxDynamicSharedMemorySize, smemB);
    conv_fused<<<BATCH, 256, smemB>>>(e, idx, conv1_w, conv1_b, conv2_w, conv2_b,
                                      W_out, b_out, outP, flatP);
}

// round 2
// speedup vs baseline: 1.8089x; 1.8089x over previous
#include <cuda_runtime.h>
#include <cstdint>

// ---------------- problem constants ----------------
#define N_RNA   2000
#define N_PROT  1512
#define NT      3512        // N_RNA + N_PROT
#define SZ_R    3000
#define FUN_IN  5603
#define H_ATT   2048
#define H_FUN   4096
#define DCOLS   512
#define BATCH   8192
#define PROTEIN 1512
#define FLATSZ  8192
#define SPLITS  8

// scratch
__device__ float g_hidden[NT * (size_t)H_FUN];                  // 57.5 MB
__device__ float g_part[SPLITS * (size_t)NT * 256];             // 28.8 MB

// ---------------- tf32 helpers ----------------
__device__ __forceinline__ uint32_t f2tf32(float x) {
    uint32_t r;
    asm("cvt.rna.tf32.f32 %0, %1;" : "=r"(r) : "f"(x));
    return r;
}
__device__ __forceinline__ void mma_tf32(float c[4],
                                         const uint32_t a[4], const uint32_t b[2]) {
    asm volatile(
        "mma.sync.aligned.m16n8k8.row.col.f32.tf32.tf32.f32 "
        "{%0,%1,%2,%3},{%4,%5,%6,%7},{%8,%9},{%0,%1,%2,%3};"
        : "+f"(c[0]), "+f"(c[1]), "+f"(c[2]), "+f"(c[3])
        : "r"(a[0]), "r"(a[1]), "r"(a[2]), "r"(a[3]), "r"(b[0]), "r"(b[1]));
}

// ---------------- big GEMM (tf32 tensor cores): C = gelu(concat(A0,A1) @ B + bias)
// CTA tile 128x128, 8 warps of 64x32, KT=16, double-buffered smem.
#define KT 16
#define ALD 20      // A smem ld (floats): conflict-free fragment loads
#define BLD 136     // B smem ld: conflict-free fragment loads

__global__ __launch_bounds__(256, 2)
void gemm_gelu_tf32(const float* __restrict__ A0, const float* __restrict__ A1,
                    int splitRow, int M, int N, int K, int lda,
                    const float* __restrict__ B, const float* __restrict__ bias,
                    float* __restrict__ C)
{
    __shared__ __align__(16) uint32_t As[2][128 * ALD];
    __shared__ __align__(16) uint32_t Bs[2][KT * BLD];

    const int tid  = threadIdx.x;
    const int lane = tid & 31;
    const int wid  = tid >> 5;
    const int mBase = (wid >> 2) * 64;     // warp row offset in tile
    const int nBase = (wid & 3) * 32;      // warp col offset in tile
    const int rowTile = blockIdx.y * 128;
    const int colBase = blockIdx.x * 128;

    // A global row for this thread's staging loads (fixed across K loop)
    const int arow = rowTile + (tid >> 1);
    const int kHalf = (tid & 1) * 8;
    const float* Arow = nullptr;
    if (arow < M)
        Arow = (arow < splitRow) ? (A0 + (size_t)arow * lda)
                                 : (A1 + (size_t)(arow - splitRow) * lda);
    // B staging coords
    const int bk0 = tid >> 5;            // 0..7
    const int bn0 = (tid & 31) * 4;      // 0..124
    const int bk1 = (tid + 256) >> 5;    // 8..15
    const int bn1 = bn0;

    float acc[4][4][4] = {};
    float areg[8];
    float4 breg[2];

    const int nk = (K + KT - 1) / KT;

    auto loadG = [&](int k0) {
        #pragma unroll
        for (int j = 0; j < 8; j++) {
            int gk = k0 + kHalf + j;
            areg[j] = (Arow && gk < K) ? __ldg(Arow + gk) : 0.f;
        }
        int gk0 = k0 + bk0, gk1 = k0 + bk1;
        breg[0] = (gk0 < K) ? *(const float4*)(B + (size_t)gk0 * N + colBase + bn0)
                            : make_float4(0.f, 0.f, 0.f, 0.f);
        breg[1] = (gk1 < K) ? *(const float4*)(B + (size_t)gk1 * N + colBase + bn1)
                            : make_float4(0.f, 0.f, 0.f, 0.f);
    };
    auto storeS = [&](int buf) {
        uint32_t* ad = &As[buf][(tid >> 1) * ALD + kHalf];
        uint4 p0 = { f2tf32(areg[0]), f2tf32(areg[1]), f2tf32(areg[2]), f2tf32(areg[3]) };
        uint4 p1 = { f2tf32(areg[4]), f2tf32(areg[5]), f2tf32(areg[6]), f2tf32(areg[7]) };
        *(uint4*)ad = p0;
        *(uint4*)(ad + 4) = p1;
        uint4 q0 = { f2tf32(breg[0].x), f2tf32(breg[0].y), f2tf32(breg[0].z), f2tf32(breg[0].w) };
        uint4 q1 = { f2tf32(breg[1].x), f2tf32(breg[1].y), f2tf32(breg[1].z), f2tf32(breg[1].w) };
        *(uint4*)&Bs[buf][bk0 * BLD + bn0] = q0;
        *(uint4*)&Bs[buf][bk1 * BLD + bn1] = q1;
    };
    auto compute = [&](int buf) {
        #pragma unroll
        for (int ks = 0; ks < 2; ks++) {
            const int k8 = ks * 8;
            uint32_t af[4][4], bf[4][2];
            #pragma unroll
            for (int mi = 0; mi < 4; mi++) {
                int m0 = mBase + mi * 16 + (lane >> 2);
                const uint32_t* ap = &As[buf][m0 * ALD + k8 + (lane & 3)];
                af[mi][0] = ap[0];
                af[mi][1] = ap[8 * ALD];
                af[mi][2] = ap[4];
                af[mi][3] = ap[8 * ALD + 4];
            }
            #pragma unroll
            for (int ni = 0; ni < 4; ni++) {
                int n0 = nBase + ni * 8 + (lane >> 2);
                const uint32_t* bp = &Bs[buf][(k8 + (lane & 3)) * BLD + n0];
                bf[ni][0] = bp[0];
                bf[ni][1] = bp[4 * BLD];
            }
            #pragma unroll
            for (int mi = 0; mi < 4; mi++)
                #pragma unroll
                for (int ni = 0; ni < 4; ni++)
                    mma_tf32(acc[mi][ni], af[mi], bf[ni]);
        }
    };

    loadG(0);
    storeS(0);
    __syncthreads();
    int buf = 0;
    for (int t = 0; t < nk; t++) {
        if (t + 1 < nk) loadG((t + 1) * KT);
        compute(buf);
        if (t + 1 < nk) storeS(buf ^ 1);
        __syncthreads();
        buf ^= 1;
    }

    // epilogue: bias + exact gelu
    #pragma unroll
    for (int mi = 0; mi < 4; mi++) {
        int r0 = rowTile + mBase + mi * 16 + (lane >> 2);
        #pragma unroll
        for (int ni = 0; ni < 4; ni++) {
            int c = colBase + nBase + ni * 8 + 2 * (lane & 3);
            float2 bb = *(const float2*)(bias + c);
            float v0 = acc[mi][ni][0] + bb.x;
            float v1 = acc[mi][ni][1] + bb.y;
            float v2 = acc[mi][ni][2] + bb.x;
            float v3 = acc[mi][ni][3] + bb.y;
            v0 = 0.5f * v0 * (1.f + erff(v0 * 0.70710678118654752f));
            v1 = 0.5f * v1 * (1.f + erff(v1 * 0.70710678118654752f));
            v2 = 0.5f * v2 * (1.f + erff(v2 * 0.70710678118654752f));
            v3 = 0.5f * v3 * (1.f + erff(v3 * 0.70710678118654752f));
            if (r0 < M)     *(float2*)(C + (size_t)r0 * N + c)       = make_float2(v0, v1);
            if (r0 + 8 < M) *(float2*)(C + (size_t)(r0 + 8) * N + c) = make_float2(v2, v3);
        }
    }
}

// ---------------- gemm2 split-K partial: part[z] += A[:,kBeg:kEnd] @ B ----------
__global__ __launch_bounds__(256)
void gemm2_partial(const float* __restrict__ A, int M, int K,
                   const float* __restrict__ B, float* __restrict__ part)
{
    __shared__ __align__(16) float As[16][64];
    __shared__ __align__(16) float Bs[16][64];
    const int N = 256;
    int tid = threadIdx.x;
    int tx = tid & 15, ty = tid >> 4;
    int rowBase = blockIdx.y * 64;
    int colBase = blockIdx.x * 64;
    int chunk = (K + SPLITS - 1) / SPLITS;
    int kBeg = blockIdx.z * chunk;
    int kEnd = min(K, kBeg + chunk);
    float acc[4][4] = {};

    for (int k0 = kBeg; k0 < kEnd; k0 += 16) {
        #pragma unroll
        for (int i = 0; i < 4; i++) {
            int lin = tid + i * 256;
            int kk = lin & 15, m = lin >> 4;
            int gr = rowBase + m, gk = k0 + kk;
            As[kk][m] = (gr < M && gk < kEnd) ? A[(size_t)gr * K + gk] : 0.f;
        }
        #pragma unroll
        for (int i = 0; i < 4; i++) {
            int lin = tid + i * 256;
            int kk = lin >> 6, n = lin & 63;
            int gk = k0 + kk;
            Bs[kk][n] = (gk < kEnd) ? B[(size_t)gk * N + colBase + n] : 0.f;
        }
        __syncthreads();
        #pragma unroll
        for (int kk = 0; kk < 16; kk++) {
            float4 a = *(const float4*)&As[kk][ty * 4];
            float4 b = *(const float4*)&Bs[kk][tx * 4];
            float av[4] = {a.x, a.y, a.z, a.w};
            float bv[4] = {b.x, b.y, b.z, b.w};
            #pragma unroll
            for (int i = 0; i < 4; i++)
                #pragma unroll
                for (int j = 0; j < 4; j++)
                    acc[i][j] += av[i] * bv[j];
        }
        __syncthreads();
    }
    float* pz = part + (size_t)blockIdx.z * M * N;
    #pragma unroll
    for (int i = 0; i < 4; i++) {
        int r = rowBase + ty * 4 + i;
        if (r >= M) continue;
        #pragma unroll
        for (int j = 0; j < 4; j++)
            pz[(size_t)r * N + colBase + tx * 4 + j] = acc[i][j];
    }
}

__global__ __launch_bounds__(256)
void gemm2_reduce(const float* __restrict__ part, const float* __restrict__ bias,
                  float* __restrict__ E, int M, int colOff)
{
    int idx = blockIdx.x * 256 + threadIdx.x;
    if (idx >= M * 256) return;
    int r = idx >> 8, c = idx & 255;
    float s = 0.f;
    #pragma unroll
    for (int z = 0; z < SPLITS; z++)
        s += part[((size_t)z * M + r) * 256 + c];
    s += bias[c];
    s = 1.f / (1.f + __expf(-s));
    E[(size_t)r * DCOLS + colOff + c] = s;
}

// ---------------- fused gather + conv1/avgpool + conv2/maxpool + tanh + out GEMM
__global__ __launch_bounds__(256)
void conv_fused(const float* __restrict__ e, const int* __restrict__ idx,
                const float* __restrict__ w1, const float* __restrict__ b1,
                const float* __restrict__ w2, const float* __restrict__ b2,
                const float* __restrict__ Wout, const float* __restrict__ bout,
                float* __restrict__ outP, float* __restrict__ flatP)
{
    extern __shared__ float sm[];
    float* xs  = sm;
    float* p1s = xs + 1032;
    float* w1s = p1s + 8320;
    float* b1s = w1s + 240;
    float* w2s = b1s + 16;
    float* b2s = w2s + 7680;
    __shared__ float redsum[8][2];

    int t = threadIdx.x;
    int b = blockIdx.x;

    for (int i = t; i < 240; i += 256)  w1s[i] = w1[i];
    for (int i = t; i < 7680; i += 256) w2s[i] = w2[i];
    if (t < 16) b1s[t] = b1[t];
    if (t < 32) b2s[t] = b2[t];

    int id  = idx[b];
    int rno = id / PROTEIN;
    int pno = id - rno * PROTEIN;
    const float* row0 = e + (size_t)rno * DCOLS;
    const float* row1 = e + (size_t)(N_RNA + pno) * DCOLS;
    for (int i = t; i < 1032; i += 256) {
        int rr = (i >= 516), c = i - rr * 516;
        float v = 0.f;
        if (c >= 2 && c < 514) v = (rr == 0 ? row0 : row1)[c - 2];
        xs[i] = v;
    }
    if (t < 128) {
        int rr = t >> 2, j = t & 3;
        int col = (j < 2) ? j : 256 + j;
        p1s[rr * 260 + col] = 0.f;
    }
    __syncthreads();

    for (int li = t; li < 8192; li += 256) {
        int c = li >> 9, ph = (li >> 8) & 1, pw = li & 255;
        const float* wc = &w1s[c * 15];
        float bb = b1s[c];
        float s = 0.f;
        #pragma unroll
        for (int d = 0; d < 4; d++) {
            int h = 2 * ph + (d >> 1);
            int w = 2 * pw + (d & 1);
            float acc = bb;
            #pragma unroll
            for (int kh = 0; kh < 3; kh++) {
                int r = h + kh - 2;
                if (r >= 0 && r < 2) {
                    #pragma unroll
                    for (int kw = 0; kw < 5; kw++)
                        acc += wc[kh * 5 + kw] * xs[r * 516 + w + kw];
                }
            }
            s += (acc >= 0.f) ? acc : 0.01f * acc;
        }
        p1s[(c * 2 + ph) * 260 + pw + 2] = 0.25f * s;
    }
    __syncthreads();

    int ph = t >> 7;
    int pw = t & 127;
    float o0 = 0.f, o1 = 0.f;
    for (int c = 0; c < 32; c++) {
        float bb = b2s[c];
        float a0 = bb, a1 = bb, a2 = bb, a3 = bb;
        const float* wc = &w2s[c * 240];
        #pragma unroll 4
        for (int ci = 0; ci < 16; ci++) {
            const float2* q0 = (const float2*)&p1s[(ci * 2 + 0) * 260 + 2 * pw];
            const float2* q1 = (const float2*)&p1s[(ci * 2 + 1) * 260 + 2 * pw];
            float2 u0 = q0[0], u1 = q0[1], u2 = q0[2];
            float2 v0 = q1[0], v1 = q1[1], v2 = q1[2];
            float r0[6] = {u0.x,u0.y,u1.x,u1.y,u2.x,u2.y};
            float r1[6] = {v0.x,v0.y,v1.x,v1.y,v2.x,v2.y};
            const float* w = wc + ci * 15;
            if (ph == 0) {
                #pragma unroll
                for (int kw = 0; kw < 5; kw++) {
                    float wA = w[10 + kw], wB = w[5 + kw];
                    a0 += wA * r0[kw];
                    a1 += wA * r0[kw + 1];
                    a2 += wB * r0[kw]     + wA * r1[kw];
                    a3 += wB * r0[kw + 1] + wA * r1[kw + 1];
                }
            } else {
                #pragma unroll
                for (int kw = 0; kw < 5; kw++) {
                    float wA = w[kw], wB = w[5 + kw];
                    a0 += wA * r0[kw]     + wB * r1[kw];
                    a1 += wA * r0[kw + 1] + wB * r1[kw + 1];
                    a2 += wA * r1[kw];
                    a3 += wA * r1[kw + 1];
                }
            }
        }
        a0 = (a0 >= 0.f) ? a0 : 0.01f * a0;
        a1 = (a1 >= 0.f) ? a1 : 0.01f * a1;
        a2 = (a2 >= 0.f) ? a2 : 0.01f * a2;
        a3 = (a3 >= 0.f) ? a3 : 0.01f * a3;
        float m  = fmaxf(fmaxf(a0, a1), fmaxf(a2, a3));
        float tv = tanhf(m);
        int fi = c * 256 + ph * 128 + pw;
        flatP[(size_t)b * FLATSZ + fi] = tv;
        o0 += tv * Wout[2 * fi];
        o1 += tv * Wout[2 * fi + 1];
    }

    #pragma unroll
    for (int off = 16; off > 0; off >>= 1) {
        o0 += __shfl_down_sync(0xffffffffu, o0, off);
        o1 += __shfl_down_sync(0xffffffffu, o1, off);
    }
    if ((t & 31) == 0) { redsum[t >> 5][0] = o0; redsum[t >> 5][1] = o1; }
    __syncthreads();
    if (t == 0) {
        float s0 = 0.f, s1 = 0.f;
        #pragma unroll
        for (int w = 0; w < 8; w++) { s0 += redsum[w][0]; s1 += redsum[w][1]; }
        outP[2 * b]     = s0 + bout[0];
        outP[2 * b + 1] = s1 + bout[1];
    }
}

// ---------------- launch ----------------
extern "C" void kernel_launch(void* const* d_in, const int* in_sizes, int n_in,
                              void* d_out, int out_size)
{
    (void)in_sizes; (void)n_in; (void)out_size;
    const float* r_att   = (const float*)d_in[0];
    const float* p_att   = (const float*)d_in[1];
    const float* r_fun   = (const float*)d_in[2];
    const float* p_fun   = (const float*)d_in[3];
    const int*   idx     = (const int*)  d_in[4];
    const float* W_att1  = (const float*)d_in[5];
    const float* b_att1  = (const float*)d_in[6];
    const float* W_att2  = (const float*)d_in[7];
    const float* b_att2  = (const float*)d_in[8];
    const float* W_fun1  = (const float*)d_in[9];
    const float* b_fun1  = (const float*)d_in[10];
    const float* W_fun2  = (const float*)d_in[11];
    const float* b_fun2  = (const float*)d_in[12];
    const float* conv1_w = (const float*)d_in[13];
    const float* conv1_b = (const float*)d_in[14];
    const float* conv2_w = (const float*)d_in[15];
    const float* conv2_b = (const float*)d_in[16];
    const float* W_out   = (const float*)d_in[17];
    const float* b_out   = (const float*)d_in[18];

    float* out   = (float*)d_out;
    float* e     = out;                              // [3512, 512]
    float* outP  = out + (size_t)NT * DCOLS;         // [8192, 2]
    float* flatP = outP + 2 * BATCH;                 // [8192, 8192]

    float* hidden = nullptr;
    float* part   = nullptr;
    cudaGetSymbolAddress((void**)&hidden, g_hidden);
    cudaGetSymbolAddress((void**)&part,   g_part);

    const int mTiles = (NT + 127) / 128;             // 28
    const int rTiles = (NT + 63) / 64;               // 55

    // ATT branch
    gemm_gelu_tf32<<<dim3(H_ATT / 128, mTiles), 256>>>(
        r_att, p_att, N_RNA, NT, H_ATT, SZ_R, SZ_R, W_att1, b_att1, hidden);
    gemm2_partial<<<dim3(4, rTiles, SPLITS), 256>>>(hidden, NT, H_ATT, W_att2, part);
    gemm2_reduce<<<(NT * 256 + 255) / 256, 256>>>(part, b_att2, e, NT, 0);

    // FUN branch
    gemm_gelu_tf32<<<dim3(H_FUN / 128, mTiles), 256>>>(
        r_fun, p_fun, N_RNA, NT, H_FUN, FUN_IN, FUN_IN, W_fun1, b_fun1, hidden);
    gemm2_partial<<<dim3(4, rTiles, SPLITS), 256>>>(hidden, NT, H_FUN, W_fun2, part);
    gemm2_reduce<<<(NT * 256 + 255) / 256, 256>>>(part, b_fun2, e, NT, 256);

    // fused conv stack
    const int smemB = 17320 * 4;
    cudaFuncSetAttribute(conv_fused, cudaFuncAttributeMaxDynamicSharedMemorySize, smemB);
    conv_fused<<<BATCH, 256, smemB>>>(e, idx, conv1_w, conv1_b, conv2_w, conv2_b,
                                      W_out, b_out, outP, flatP);
}

// round 7
// speedup vs baseline: 2.1821x; 1.2063x over previous
#include <cuda_runtime.h>
#include <cstdint>

// ---------------- problem constants ----------------
#define N_RNA   2000
#define N_PROT  1512
#define NT      3512
#define SZ_R    3000
#define FUN_IN  5603
#define H_ATT   2048
#define H_FUN   4096
#define DCOLS   512
#define BATCH   8192
#define PROTEIN 1512
#define FLATSZ  8192
#define SPLITS2 4

#define M_PAD   3584            // 28 * 128
#define KP_ATT  3008            // 16-float multiple >= 3000
#define KP_FUN  5616            // 16-float multiple >= 5603

// scratch
__device__ float g_hidden[NT * (size_t)H_FUN];                 // 57.5 MB
__device__ float g_part[SPLITS2 * (size_t)NT * 256];           // 14.4 MB
__device__ float g_A[(size_t)M_PAD * KP_FUN];                  // 80.5 MB

// ---------------- helpers ----------------
__device__ __forceinline__ uint32_t smem_u32(const void* p) {
    uint32_t a;
    asm("{ .reg .u64 t; cvta.to.shared.u64 t, %1; cvt.u32.u64 %0, t; }" : "=r"(a) : "l"(p));
    return a;
}
__device__ __forceinline__ void mma_tf32(float c[4],
                                         const uint32_t a[4], const uint32_t b[2]) {
    asm volatile(
        "mma.sync.aligned.m16n8k8.row.col.f32.tf32.tf32.f32 "
        "{%0,%1,%2,%3},{%4,%5,%6,%7},{%8,%9},{%0,%1,%2,%3};"
        : "+f"(c[0]), "+f"(c[1]), "+f"(c[2]), "+f"(c[3])
        : "r"(a[0]), "r"(a[1]), "r"(a[2]), "r"(a[3]), "r"(b[0]), "r"(b[1]));
}
#define CPA16(dst, src) \
    asm volatile("cp.async.ca.shared.global [%0], [%1], 16;" :: "r"(dst), "l"(src))
#define CPA16Z(dst, src, sz) \
    asm volatile("cp.async.ca.shared.global [%0], [%1], 16, %2;" \
                 :: "r"(dst), "l"(src), "r"(sz))
#define CP_COMMIT() asm volatile("cp.async.commit_group;" ::: "memory")

// smem per stage: A [128][20] floats (10240 B) + B [16][136] floats (8704 B)
#define KT        16
#define ALD       20
#define BLD       136
#define A_BYTES   10240
#define STG_BYTES 18944
#define NSTAGE    3

// =====================================================================
// tf32 mma.sync GEMM — round-2 validated compute core, cp.async staging.
// Tile 128(M) x 128(N), KT=16, 3-stage ring, 8 warps of 64x32.
//   A row-major [*, lda] — 16B-aligned rows (packed or hidden).
//   mode 0: C[r][n]       = gelu(acc + bias[n])   (grid.z == 1, full K)
//   mode 1: part[z][r][n] = acc over K chunk z    (split-K, kLen | 16)
// =====================================================================
__global__ __launch_bounds__(256, 2)
void gemm_tf32(const float* __restrict__ A, int lda, int Mreal,
               const float* __restrict__ B, int N, int Kreal, int kLen,
               const float* __restrict__ bias, float* __restrict__ Cout,
               int mode)
{
    extern __shared__ __align__(16) char smemRaw[];
    uint32_t* smemW = (uint32_t*)smemRaw;
    const uint32_t smB = smem_u32(smemRaw);

    const int tid  = threadIdx.x;
    const int lane = tid & 31;
    const int wid  = tid >> 5;
    const int mWarp = (wid >> 2) * 64;
    const int nWarp = (wid & 3) * 32;
    const int rowTile = blockIdx.y * 128;
    const int colBase = blockIdx.x * 128;

    const int kBeg = blockIdx.z * kLen;
    const int nk   = (min(kBeg + kLen, Kreal) - kBeg + KT - 1) / KT;

    // ---- A staging coords: thread -> (row, 8-float half) ----
    const int aRow  = tid >> 1;
    const int aHalf = (tid & 1) * 8;
    int gRow = rowTile + aRow; if (gRow >= Mreal) gRow = Mreal - 1;
    const float* Arow = A + (size_t)gRow * lda;          // 16B-aligned row
    const uint32_t aDst = (uint32_t)(aRow * ALD + aHalf) * 4u;

    // ---- B staging coords: thread -> (two k rows, 4 floats) ----
    const int bk0 = tid >> 5;            // 0..7 (and +8)
    const int bn4 = lane * 4;            // 0..124

    float acc[4][4][4] = {};

    auto stage = [&](int buf, int k0) {
        uint32_t base = smB + (uint32_t)buf * STG_BYTES;
        // A: two aligned 16B chunks, always in-bounds (padded rows)
        CPA16(base + aDst,       Arow + k0 + aHalf);
        CPA16(base + aDst + 16u, Arow + k0 + aHalf + 4);
        // B: rows bk0 and bk0+8, 16B each, zero-filled past Kreal
        #pragma unroll
        for (int j = 0; j < 2; j++) {
            int kk = bk0 + j * 8;
            int gk = k0 + kk;
            uint32_t sz = (gk < Kreal) ? 16u : 0u;
            int gkc = (gk < Kreal) ? gk : Kreal - 1;
            CPA16Z(base + A_BYTES + (uint32_t)(kk * BLD + bn4) * 4u,
                   B + (size_t)gkc * N + colBase + bn4, sz);
        }
    };

    stage(0, kBeg); CP_COMMIT();
    if (nk > 1) { stage(1, kBeg + KT); CP_COMMIT(); }

    for (int t = 0; t < nk; t++) {
        if (t + 1 < nk) asm volatile("cp.async.wait_group 1;" ::: "memory");
        else            asm volatile("cp.async.wait_group 0;" ::: "memory");
        __syncthreads();

        const uint32_t* As = smemW + (size_t)(t % NSTAGE) * (STG_BYTES / 4);
        const uint32_t* Bs = As + (A_BYTES / 4);

        #pragma unroll
        for (int ks = 0; ks < 2; ks++) {
            const int k8 = ks * 8;
            uint32_t af[4][4], bf[4][2];
            #pragma unroll
            for (int mi = 0; mi < 4; mi++) {
                int m0 = mWarp + mi * 16 + (lane >> 2);
                const uint32_t* ap = &As[m0 * ALD + k8 + (lane & 3)];
                af[mi][0] = ap[0];
                af[mi][1] = ap[8 * ALD];
                af[mi][2] = ap[4];
                af[mi][3] = ap[8 * ALD + 4];
            }
            #pragma unroll
            for (int ni = 0; ni < 4; ni++) {
                int n0 = nWarp + ni * 8 + (lane >> 2);
                const uint32_t* bp = &Bs[(k8 + (lane & 3)) * BLD + n0];
                bf[ni][0] = bp[0];
                bf[ni][1] = bp[4 * BLD];
            }
            #pragma unroll
            for (int mi = 0; mi < 4; mi++)
                #pragma unroll
                for (int ni = 0; ni < 4; ni++)
                    mma_tf32(acc[mi][ni], af[mi], bf[ni]);
        }
        __syncthreads();
        if (t + 2 < nk) {
            stage((t + 2) % NSTAGE, kBeg + (t + 2) * KT);
            CP_COMMIT();
        }
    }

    // ---- epilogue (round-2 validated mapping) ----
    float* outBase = (mode == 1) ? (Cout + (size_t)blockIdx.z * Mreal * N) : Cout;
    #pragma unroll
    for (int mi = 0; mi < 4; mi++) {
        int r0 = rowTile + mWarp + mi * 16 + (lane >> 2);
        #pragma unroll
        for (int ni = 0; ni < 4; ni++) {
            int c = colBase + nWarp + ni * 8 + 2 * (lane & 3);
            float v0 = acc[mi][ni][0], v1 = acc[mi][ni][1];
            float v2 = acc[mi][ni][2], v3 = acc[mi][ni][3];
            if (mode == 0) {
                float2 bb = *(const float2*)(bias + c);
                v0 += bb.x; v1 += bb.y; v2 += bb.x; v3 += bb.y;
                v0 = 0.5f * v0 * (1.f + erff(v0 * 0.70710678118654752f));
                v1 = 0.5f * v1 * (1.f + erff(v1 * 0.70710678118654752f));
                v2 = 0.5f * v2 * (1.f + erff(v2 * 0.70710678118654752f));
                v3 = 0.5f * v3 * (1.f + erff(v3 * 0.70710678118654752f));
            }
            if (r0 < Mreal)     *(float2*)(outBase + (size_t)r0 * N + c)       = make_float2(v0, v1);
            if (r0 + 8 < Mreal) *(float2*)(outBase + (size_t)(r0 + 8) * N + c) = make_float2(v2, v3);
        }
    }
}

// ---------------- pack A: concat rows -> g_A[M_PAD][Kpad], zero-padded ----------
// scalar loads (alignment-immune), aligned float4 stores
__global__ __launch_bounds__(256)
void pack_A(const float* __restrict__ A0, const float* __restrict__ A1,
            int split, int Kreal, int Kpad, float* __restrict__ dst)
{
    size_t i = (size_t)blockIdx.x * 256 + threadIdx.x;
    size_t tot = (size_t)M_PAD * (Kpad >> 2);
    if (i >= tot) return;
    int r = (int)(i / (Kpad >> 2));
    int k = (int)(i % (Kpad >> 2)) * 4;
    float4 v = make_float4(0.f, 0.f, 0.f, 0.f);
    if (r < NT) {
        const float* src = (r < split) ? (A0 + (size_t)r * Kreal)
                                       : (A1 + (size_t)(r - split) * Kreal);
        if (k     < Kreal) v.x = __ldg(src + k);
        if (k + 1 < Kreal) v.y = __ldg(src + k + 1);
        if (k + 2 < Kreal) v.z = __ldg(src + k + 2);
        if (k + 3 < Kreal) v.w = __ldg(src + k + 3);
    }
    *(float4*)(dst + (size_t)r * Kpad + k) = v;
}

// ---------------- split-K reduce + sigmoid -> e columns ----------------
__global__ __launch_bounds__(256)
void gemm2_reduce(const float* __restrict__ part, const float* __restrict__ bias,
                  float* __restrict__ E, int M, int colOff)
{
    int idx = blockIdx.x * 256 + threadIdx.x;
    if (idx >= M * 256) return;
    int r = idx >> 8, c = idx & 255;
    float s = 0.f;
    #pragma unroll
    for (int z = 0; z < SPLITS2; z++)
        s += part[((size_t)z * M + r) * 256 + c];
    s += bias[c];
    s = 1.f / (1.f + __expf(-s));
    E[(size_t)r * DCOLS + colOff + c] = s;
}

// ---------------- fused conv stack (validated in rounds 1-2) ----------------
__global__ __launch_bounds__(256)
void conv_fused(const float* __restrict__ e, const int* __restrict__ idx,
                const float* __restrict__ w1, const float* __restrict__ b1,
                const float* __restrict__ w2, const float* __restrict__ b2,
                const float* __restrict__ Wout, const float* __restrict__ bout,
                float* __restrict__ outP, float* __restrict__ flatP)
{
    extern __shared__ float sm[];
    float* xs  = sm;
    float* p1s = xs + 1032;
    float* w1s = p1s + 8320;
    float* b1s = w1s + 240;
    float* w2s = b1s + 16;
    float* b2s = w2s + 7680;
    __shared__ float redsum[8][2];

    int t = threadIdx.x;
    int b = blockIdx.x;

    for (int i = t; i < 240; i += 256)  w1s[i] = w1[i];
    for (int i = t; i < 7680; i += 256) w2s[i] = w2[i];
    if (t < 16) b1s[t] = b1[t];
    if (t < 32) b2s[t] = b2[t];

    int id  = idx[b];
    int rno = id / PROTEIN;
    int pno = id - rno * PROTEIN;
    const float* row0 = e + (size_t)rno * DCOLS;
    const float* row1 = e + (size_t)(N_RNA + pno) * DCOLS;
    for (int i = t; i < 1032; i += 256) {
        int rr = (i >= 516), c = i - rr * 516;
        float v = 0.f;
        if (c >= 2 && c < 514) v = (rr == 0 ? row0 : row1)[c - 2];
        xs[i] = v;
    }
    if (t < 128) {
        int rr = t >> 2, j = t & 3;
        int col = (j < 2) ? j : 256 + j;
        p1s[rr * 260 + col] = 0.f;
    }
    __syncthreads();

    for (int li = t; li < 8192; li += 256) {
        int c = li >> 9, ph = (li >> 8) & 1, pw = li & 255;
        const float* wc = &w1s[c * 15];
        float bb = b1s[c];
        float s = 0.f;
        #pragma unroll
        for (int d = 0; d < 4; d++) {
            int h = 2 * ph + (d >> 1);
            int w = 2 * pw + (d & 1);
            float acc = bb;
            #pragma unroll
            for (int kh = 0; kh < 3; kh++) {
                int r = h + kh - 2;
                if (r >= 0 && r < 2) {
                    #pragma unroll
                    for (int kw = 0; kw < 5; kw++)
                        acc += wc[kh * 5 + kw] * xs[r * 516 + w + kw];
                }
            }
            s += (acc >= 0.f) ? acc : 0.01f * acc;
        }
        p1s[(c * 2 + ph) * 260 + pw + 2] = 0.25f * s;
    }
    __syncthreads();

    int ph = t >> 7;
    int pw = t & 127;
    float o0 = 0.f, o1 = 0.f;
    for (int c = 0; c < 32; c++) {
        float bb = b2s[c];
        float a0 = bb, a1 = bb, a2 = bb, a3 = bb;
        const float* wc = &w2s[c * 240];
        #pragma unroll 4
        for (int ci = 0; ci < 16; ci++) {
            const float2* q0 = (const float2*)&p1s[(ci * 2 + 0) * 260 + 2 * pw];
            const float2* q1 = (const float2*)&p1s[(ci * 2 + 1) * 260 + 2 * pw];
            float2 u0 = q0[0], u1 = q0[1], u2 = q0[2];
            float2 v0 = q1[0], v1 = q1[1], v2 = q1[2];
            float r0[6] = {u0.x,u0.y,u1.x,u1.y,u2.x,u2.y};
            float r1[6] = {v0.x,v0.y,v1.x,v1.y,v2.x,v2.y};
            const float* w = wc + ci * 15;
            if (ph == 0) {
                #pragma unroll
                for (int kw = 0; kw < 5; kw++) {
                    float wA = w[10 + kw], wB = w[5 + kw];
                    a0 += wA * r0[kw];
                    a1 += wA * r0[kw + 1];
                    a2 += wB * r0[kw]     + wA * r1[kw];
                    a3 += wB * r0[kw + 1] + wA * r1[kw + 1];
                }
            } else {
                #pragma unroll
                for (int kw = 0; kw < 5; kw++) {
                    float wA = w[kw], wB = w[5 + kw];
                    a0 += wA * r0[kw]     + wB * r1[kw];
                    a1 += wA * r0[kw + 1] + wB * r1[kw + 1];
                    a2 += wA * r1[kw];
                    a3 += wA * r1[kw + 1];
                }
            }
        }
        a0 = (a0 >= 0.f) ? a0 : 0.01f * a0;
        a1 = (a1 >= 0.f) ? a1 : 0.01f * a1;
        a2 = (a2 >= 0.f) ? a2 : 0.01f * a2;
        a3 = (a3 >= 0.f) ? a3 : 0.01f * a3;
        float m  = fmaxf(fmaxf(a0, a1), fmaxf(a2, a3));
        float tv = tanhf(m);
        int fi = c * 256 + ph * 128 + pw;
        flatP[(size_t)b * FLATSZ + fi] = tv;
        o0 += tv * Wout[2 * fi];
        o1 += tv * Wout[2 * fi + 1];
    }

    #pragma unroll
    for (int off = 16; off > 0; off >>= 1) {
        o0 += __shfl_down_sync(0xffffffffu, o0, off);
        o1 += __shfl_down_sync(0xffffffffu, o1, off);
    }
    if ((t & 31) == 0) { redsum[t >> 5][0] = o0; redsum[t >> 5][1] = o1; }
    __syncthreads();
    if (t == 0) {
        float s0 = 0.f, s1 = 0.f;
        #pragma unroll
        for (int w = 0; w < 8; w++) { s0 += redsum[w][0]; s1 += redsum[w][1]; }
        outP[2 * b]     = s0 + bout[0];
        outP[2 * b + 1] = s1 + bout[1];
    }
}

// ---------------- launch ----------------
extern "C" void kernel_launch(void* const* d_in, const int* in_sizes, int n_in,
                              void* d_out, int out_size)
{
    (void)in_sizes; (void)n_in; (void)out_size;
    const float* r_att   = (const float*)d_in[0];
    const float* p_att   = (const float*)d_in[1];
    const float* r_fun   = (const float*)d_in[2];
    const float* p_fun   = (const float*)d_in[3];
    const int*   idx     = (const int*)  d_in[4];
    const float* W_att1  = (const float*)d_in[5];
    const float* b_att1  = (const float*)d_in[6];
    const float* W_att2  = (const float*)d_in[7];
    const float* b_att2  = (const float*)d_in[8];
    const float* W_fun1  = (const float*)d_in[9];
    const float* b_fun1  = (const float*)d_in[10];
    const float* W_fun2  = (const float*)d_in[11];
    const float* b_fun2  = (const float*)d_in[12];
    const float* conv1_w = (const float*)d_in[13];
    const float* conv1_b = (const float*)d_in[14];
    const float* conv2_w = (const float*)d_in[15];
    const float* conv2_b = (const float*)d_in[16];
    const float* W_out   = (const float*)d_in[17];
    const float* b_out   = (const float*)d_in[18];

    float* out   = (float*)d_out;
    float* e     = out;                              // [3512, 512]
    float* outP  = out + (size_t)NT * DCOLS;         // [8192, 2]
    float* flatP = outP + 2 * BATCH;                 // [8192, 8192]

    float *hidden, *part, *Apk;
    cudaGetSymbolAddress((void**)&hidden, g_hidden);
    cudaGetSymbolAddress((void**)&part,   g_part);
    cudaGetSymbolAddress((void**)&Apk,    g_A);

    const int gemmSmem = NSTAGE * STG_BYTES + 16;    // 56848
    cudaFuncSetAttribute(gemm_tf32, cudaFuncAttributeMaxDynamicSharedMemorySize, gemmSmem);

    const int mT = (NT + 127) / 128;                 // 28

    // ===== ATT branch =====
    {
        size_t n4 = (size_t)M_PAD * (KP_ATT / 4);
        pack_A<<<(unsigned)((n4 + 255) / 256), 256>>>(r_att, p_att, N_RNA, SZ_R, KP_ATT, Apk);
        gemm_tf32<<<dim3(H_ATT / 128, mT, 1), 256, gemmSmem>>>(
            Apk, KP_ATT, NT, W_att1, H_ATT, SZ_R, KP_ATT, b_att1, hidden, 0);
        gemm_tf32<<<dim3(2, mT, SPLITS2), 256, gemmSmem>>>(
            hidden, H_ATT, NT, W_att2, 256, H_ATT, H_ATT / SPLITS2, nullptr, part, 1);
        gemm2_reduce<<<(NT * 256 + 255) / 256, 256>>>(part, b_att2, e, NT, 0);
    }
    // ===== FUN branch =====
    {
        size_t n4 = (size_t)M_PAD * (KP_FUN / 4);
        pack_A<<<(unsigned)((n4 + 255) / 256), 256>>>(r_fun, p_fun, N_RNA, FUN_IN, KP_FUN, Apk);
        gemm_tf32<<<dim3(H_FUN / 128, mT, 1), 256, gemmSmem>>>(
            Apk, KP_FUN, NT, W_fun1, H_FUN, FUN_IN, KP_FUN, b_fun1, hidden, 0);
        gemm_tf32<<<dim3(2, mT, SPLITS2), 256, gemmSmem>>>(
            hidden, H_FUN, NT, W_fun2, 256, H_FUN, H_FUN / SPLITS2, nullptr, part, 1);
        gemm2_reduce<<<(NT * 256 + 255) / 256, 256>>>(part, b_fun2, e, NT, 256);
    }

    // fused conv stack
    const int convSmem = 17320 * 4;
    cudaFuncSetAttribute(conv_fused, cudaFuncAttributeMaxDynamicSharedMemorySize, convSmem);
    conv_fused<<<BATCH, 256, convSmem>>>(e, idx, conv1_w, conv1_b, conv2_w, conv2_b,
                                         W_out, b_out, outP, flatP);
}

// round 8
// speedup vs baseline: 2.2300x; 1.0220x over previous
#include <cuda_runtime.h>
#include <cstdint>

// ---------------- problem constants ----------------
#define N_RNA   2000
#define N_PROT  1512
#define NT      3512
#define SZ_R    3000
#define FUN_IN  5603
#define H_ATT   2048
#define H_FUN   4096
#define DCOLS   512
#define BATCH   8192
#define PROTEIN 1512
#define FLATSZ  8192
#define SPLITS2 4

#define M_PAD   3584            // 28 * 128
#define KP_ATT  3008            // 16-float multiple >= 3000
#define KP_FUN  5616            // 16-float multiple >= 5603

// scratch
__device__ float g_hidden[NT * (size_t)H_FUN];                 // 57.5 MB
__device__ float g_part[SPLITS2 * (size_t)NT * 256];           // 14.4 MB
__device__ float g_A[(size_t)M_PAD * KP_FUN];                  // 80.5 MB

// ---------------- helpers ----------------
__device__ __forceinline__ uint32_t smem_u32(const void* p) {
    uint32_t a;
    asm("{ .reg .u64 t; cvta.to.shared.u64 t, %1; cvt.u32.u64 %0, t; }" : "=r"(a) : "l"(p));
    return a;
}
__device__ __forceinline__ void mma_tf32(float c[4],
                                         const uint32_t a[4], const uint32_t b[2]) {
    asm volatile(
        "mma.sync.aligned.m16n8k8.row.col.f32.tf32.tf32.f32 "
        "{%0,%1,%2,%3},{%4,%5,%6,%7},{%8,%9},{%0,%1,%2,%3};"
        : "+f"(c[0]), "+f"(c[1]), "+f"(c[2]), "+f"(c[3])
        : "r"(a[0]), "r"(a[1]), "r"(a[2]), "r"(a[3]), "r"(b[0]), "r"(b[1]));
}
#define CPA16(dst, src) \
    asm volatile("cp.async.ca.shared.global [%0], [%1], 16;" :: "r"(dst), "l"(src))
#define CPA16Z(dst, src, sz) \
    asm volatile("cp.async.ca.shared.global [%0], [%1], 16, %2;" \
                 :: "r"(dst), "l"(src), "r"(sz))
#define CP_COMMIT() asm volatile("cp.async.commit_group;" ::: "memory")

// packed f32x2 (Blackwell): FFMA2 path, PTX-only
#define PK2(d, lo, hi) \
    asm("mov.b64 %0, {%1, %2};" : "=l"(d) : "f"(lo), "f"(hi))
#define UPK2(lo, hi, s) \
    asm("mov.b64 {%0, %1}, %2;" : "=f"(lo), "=f"(hi) : "l"(s))
#define FMA2(d, a, b) \
    asm("fma.rn.f32x2 %0, %1, %2, %0;" : "+l"(d) : "l"(a), "l"(b))

// smem per stage: A [128][20] floats (10240 B) + B [16][136] floats (8704 B)
#define KT        16
#define ALD       20
#define BLD       136
#define A_BYTES   10240
#define STG_BYTES 18944
#define NSTAGE    3

// =====================================================================
// tf32 mma.sync GEMM — round-2 validated compute core, cp.async staging.
// (unchanged from round 7)
// =====================================================================
__global__ __launch_bounds__(256, 2)
void gemm_tf32(const float* __restrict__ A, int lda, int Mreal,
               const float* __restrict__ B, int N, int Kreal, int kLen,
               const float* __restrict__ bias, float* __restrict__ Cout,
               int mode)
{
    extern __shared__ __align__(16) char smemRaw[];
    uint32_t* smemW = (uint32_t*)smemRaw;
    const uint32_t smB = smem_u32(smemRaw);

    const int tid  = threadIdx.x;
    const int lane = tid & 31;
    const int wid  = tid >> 5;
    const int mWarp = (wid >> 2) * 64;
    const int nWarp = (wid & 3) * 32;
    const int rowTile = blockIdx.y * 128;
    const int colBase = blockIdx.x * 128;

    const int kBeg = blockIdx.z * kLen;
    const int nk   = (min(kBeg + kLen, Kreal) - kBeg + KT - 1) / KT;

    const int aRow  = tid >> 1;
    const int aHalf = (tid & 1) * 8;
    int gRow = rowTile + aRow; if (gRow >= Mreal) gRow = Mreal - 1;
    const float* Arow = A + (size_t)gRow * lda;
    const uint32_t aDst = (uint32_t)(aRow * ALD + aHalf) * 4u;

    const int bk0 = tid >> 5;
    const int bn4 = lane * 4;

    float acc[4][4][4] = {};

    auto stage = [&](int buf, int k0) {
        uint32_t base = smB + (uint32_t)buf * STG_BYTES;
        CPA16(base + aDst,       Arow + k0 + aHalf);
        CPA16(base + aDst + 16u, Arow + k0 + aHalf + 4);
        #pragma unroll
        for (int j = 0; j < 2; j++) {
            int kk = bk0 + j * 8;
            int gk = k0 + kk;
            uint32_t sz = (gk < Kreal) ? 16u : 0u;
            int gkc = (gk < Kreal) ? gk : Kreal - 1;
            CPA16Z(base + A_BYTES + (uint32_t)(kk * BLD + bn4) * 4u,
                   B + (size_t)gkc * N + colBase + bn4, sz);
        }
    };

    stage(0, kBeg); CP_COMMIT();
    if (nk > 1) { stage(1, kBeg + KT); CP_COMMIT(); }

    for (int t = 0; t < nk; t++) {
        if (t + 1 < nk) asm volatile("cp.async.wait_group 1;" ::: "memory");
        else            asm volatile("cp.async.wait_group 0;" ::: "memory");
        __syncthreads();

        const uint32_t* As = smemW + (size_t)(t % NSTAGE) * (STG_BYTES / 4);
        const uint32_t* Bs = As + (A_BYTES / 4);

        #pragma unroll
        for (int ks = 0; ks < 2; ks++) {
            const int k8 = ks * 8;
            uint32_t af[4][4], bf[4][2];
            #pragma unroll
            for (int mi = 0; mi < 4; mi++) {
                int m0 = mWarp + mi * 16 + (lane >> 2);
                const uint32_t* ap = &As[m0 * ALD + k8 + (lane & 3)];
                af[mi][0] = ap[0];
                af[mi][1] = ap[8 * ALD];
                af[mi][2] = ap[4];
                af[mi][3] = ap[8 * ALD + 4];
            }
            #pragma unroll
            for (int ni = 0; ni < 4; ni++) {
                int n0 = nWarp + ni * 8 + (lane >> 2);
                const uint32_t* bp = &Bs[(k8 + (lane & 3)) * BLD + n0];
                bf[ni][0] = bp[0];
                bf[ni][1] = bp[4 * BLD];
            }
            #pragma unroll
            for (int mi = 0; mi < 4; mi++)
                #pragma unroll
                for (int ni = 0; ni < 4; ni++)
                    mma_tf32(acc[mi][ni], af[mi], bf[ni]);
        }
        __syncthreads();
        if (t + 2 < nk) {
            stage((t + 2) % NSTAGE, kBeg + (t + 2) * KT);
            CP_COMMIT();
        }
    }

    float* outBase = (mode == 1) ? (Cout + (size_t)blockIdx.z * Mreal * N) : Cout;
    #pragma unroll
    for (int mi = 0; mi < 4; mi++) {
        int r0 = rowTile + mWarp + mi * 16 + (lane >> 2);
        #pragma unroll
        for (int ni = 0; ni < 4; ni++) {
            int c = colBase + nWarp + ni * 8 + 2 * (lane & 3);
            float v0 = acc[mi][ni][0], v1 = acc[mi][ni][1];
            float v2 = acc[mi][ni][2], v3 = acc[mi][ni][3];
            if (mode == 0) {
                float2 bb = *(const float2*)(bias + c);
                v0 += bb.x; v1 += bb.y; v2 += bb.x; v3 += bb.y;
                v0 = 0.5f * v0 * (1.f + erff(v0 * 0.70710678118654752f));
                v1 = 0.5f * v1 * (1.f + erff(v1 * 0.70710678118654752f));
                v2 = 0.5f * v2 * (1.f + erff(v2 * 0.70710678118654752f));
                v3 = 0.5f * v3 * (1.f + erff(v3 * 0.70710678118654752f));
            }
            if (r0 < Mreal)     *(float2*)(outBase + (size_t)r0 * N + c)       = make_float2(v0, v1);
            if (r0 + 8 < Mreal) *(float2*)(outBase + (size_t)(r0 + 8) * N + c) = make_float2(v2, v3);
        }
    }
}

// ---------------- pack A (unchanged) ----------------
__global__ __launch_bounds__(256)
void pack_A(const float* __restrict__ A0, const float* __restrict__ A1,
            int split, int Kreal, int Kpad, float* __restrict__ dst)
{
    size_t i = (size_t)blockIdx.x * 256 + threadIdx.x;
    size_t tot = (size_t)M_PAD * (Kpad >> 2);
    if (i >= tot) return;
    int r = (int)(i / (Kpad >> 2));
    int k = (int)(i % (Kpad >> 2)) * 4;
    float4 v = make_float4(0.f, 0.f, 0.f, 0.f);
    if (r < NT) {
        const float* src = (r < split) ? (A0 + (size_t)r * Kreal)
                                       : (A1 + (size_t)(r - split) * Kreal);
        if (k     < Kreal) v.x = __ldg(src + k);
        if (k + 1 < Kreal) v.y = __ldg(src + k + 1);
        if (k + 2 < Kreal) v.z = __ldg(src + k + 2);
        if (k + 3 < Kreal) v.w = __ldg(src + k + 3);
    }
    *(float4*)(dst + (size_t)r * Kpad + k) = v;
}

// ---------------- split-K reduce + sigmoid (unchanged) ----------------
__global__ __launch_bounds__(256)
void gemm2_reduce(const float* __restrict__ part, const float* __restrict__ bias,
                  float* __restrict__ E, int M, int colOff)
{
    int idx = blockIdx.x * 256 + threadIdx.x;
    if (idx >= M * 256) return;
    int r = idx >> 8, c = idx & 255;
    float s = 0.f;
    #pragma unroll
    for (int z = 0; z < SPLITS2; z++)
        s += part[((size_t)z * M + r) * 256 + c];
    s += bias[c];
    s = 1.f / (1.f + __expf(-s));
    E[(size_t)r * DCOLS + colOff + c] = s;
}

// ---------------- fused conv stack: conv2 on packed f32x2 (FFMA2) ----------------
__global__ __launch_bounds__(256)
void conv_fused(const float* __restrict__ e, const int* __restrict__ idx,
                const float* __restrict__ w1, const float* __restrict__ b1,
                const float* __restrict__ w2, const float* __restrict__ b2,
                const float* __restrict__ Wout, const float* __restrict__ bout,
                float* __restrict__ outP, float* __restrict__ flatP)
{
    extern __shared__ float sm[];
    float* xs  = sm;             // 1032
    float* p1s = xs + 1032;      // 8320
    float* w1s = p1s + 8320;     // 240
    float* b1s = w1s + 240;      // 16
    float* w2d = b1s + 16;       // 15360 (duplicated [w,w] pairs)
    float* b2s = w2d + 15360;    // 32    -> total 25000 floats = 100000 B
    __shared__ float redsum[8][2];

    int t = threadIdx.x;
    int b = blockIdx.x;

    for (int i = t; i < 240; i += 256)  w1s[i] = w1[i];
    for (int i = t; i < 7680; i += 256) {
        float w = w2[i];
        ((float2*)w2d)[i] = make_float2(w, w);       // duplicated pair, 8B aligned
    }
    if (t < 16) b1s[t] = b1[t];
    if (t < 32) b2s[t] = b2[t];

    int id  = idx[b];
    int rno = id / PROTEIN;
    int pno = id - rno * PROTEIN;
    const float* row0 = e + (size_t)rno * DCOLS;
    const float* row1 = e + (size_t)(N_RNA + pno) * DCOLS;
    for (int i = t; i < 1032; i += 256) {
        int rr = (i >= 516), c = i - rr * 516;
        float v = 0.f;
        if (c >= 2 && c < 514) v = (rr == 0 ? row0 : row1)[c - 2];
        xs[i] = v;
    }
    if (t < 128) {
        int rr = t >> 2, j = t & 3;
        int col = (j < 2) ? j : 256 + j;
        p1s[rr * 260 + col] = 0.f;
    }
    __syncthreads();

    // conv1 + leaky + avgpool (unchanged, validated)
    for (int li = t; li < 8192; li += 256) {
        int c = li >> 9, ph = (li >> 8) & 1, pw = li & 255;
        const float* wc = &w1s[c * 15];
        float bb = b1s[c];
        float s = 0.f;
        #pragma unroll
        for (int d = 0; d < 4; d++) {
            int h = 2 * ph + (d >> 1);
            int w = 2 * pw + (d & 1);
            float acc = bb;
            #pragma unroll
            for (int kh = 0; kh < 3; kh++) {
                int r = h + kh - 2;
                if (r >= 0 && r < 2) {
                    #pragma unroll
                    for (int kw = 0; kw < 5; kw++)
                        acc += wc[kh * 5 + kw] * xs[r * 516 + w + kw];
                }
            }
            s += (acc >= 0.f) ? acc : 0.01f * acc;
        }
        p1s[(c * 2 + ph) * 260 + pw + 2] = 0.25f * s;
    }
    __syncthreads();

    // conv2 + leaky + maxpool + tanh + out-GEMM — FFMA2, 8-channel blocks
    int ph = t >> 7;        // uniform per warp
    int pw = t & 127;
    float o0 = 0.f, o1 = 0.f;

    for (int cb = 0; cb < 32; cb += 8) {
        unsigned long long acc01[8], acc23[8];
        #pragma unroll
        for (int j = 0; j < 8; j++) {
            float bb = b2s[cb + j];
            PK2(acc01[j], bb, bb);
            acc23[j] = acc01[j];
        }
        for (int ci = 0; ci < 16; ci++) {
            const float2* q0 = (const float2*)&p1s[(ci * 2 + 0) * 260 + 2 * pw];
            const float2* q1 = (const float2*)&p1s[(ci * 2 + 1) * 260 + 2 * pw];
            float2 u0 = q0[0], u1 = q0[1], u2 = q0[2];
            float2 v0 = q1[0], v1 = q1[1], v2 = q1[2];
            unsigned long long p0[5], p1p[5];
            PK2(p0[0],  u0.x, u0.y); PK2(p0[1],  u0.y, u1.x); PK2(p0[2],  u1.x, u1.y);
            PK2(p0[3],  u1.y, u2.x); PK2(p0[4],  u2.x, u2.y);
            PK2(p1p[0], v0.x, v0.y); PK2(p1p[1], v0.y, v1.x); PK2(p1p[2], v1.x, v1.y);
            PK2(p1p[3], v1.y, v2.x); PK2(p1p[4], v2.x, v2.y);
            #pragma unroll
            for (int j = 0; j < 8; j++) {
                const unsigned long long* wd =
                    (const unsigned long long*)&w2d[((cb + j) * 240 + ci * 15) * 2];
                if (ph == 0) {
                    #pragma unroll
                    for (int kw = 0; kw < 5; kw++) {
                        unsigned long long wA = wd[10 + kw], wB = wd[5 + kw];
                        FMA2(acc01[j], wA, p0[kw]);
                        FMA2(acc23[j], wB, p0[kw]);
                        FMA2(acc23[j], wA, p1p[kw]);
                    }
                } else {
                    #pragma unroll
                    for (int kw = 0; kw < 5; kw++) {
                        unsigned long long wA = wd[kw], wB = wd[5 + kw];
                        FMA2(acc01[j], wA, p0[kw]);
                        FMA2(acc01[j], wB, p1p[kw]);
                        FMA2(acc23[j], wA, p1p[kw]);
                    }
                }
            }
        }
        #pragma unroll
        for (int j = 0; j < 8; j++) {
            float a0, a1, a2, a3;
            UPK2(a0, a1, acc01[j]);
            UPK2(a2, a3, acc23[j]);
            a0 = (a0 >= 0.f) ? a0 : 0.01f * a0;
            a1 = (a1 >= 0.f) ? a1 : 0.01f * a1;
            a2 = (a2 >= 0.f) ? a2 : 0.01f * a2;
            a3 = (a3 >= 0.f) ? a3 : 0.01f * a3;
            float m  = fmaxf(fmaxf(a0, a1), fmaxf(a2, a3));
            float tv = tanhf(m);
            int fi = (cb + j) * 256 + ph * 128 + pw;
            flatP[(size_t)b * FLATSZ + fi] = tv;
            o0 += tv * Wout[2 * fi];
            o1 += tv * Wout[2 * fi + 1];
        }
    }

    #pragma unroll
    for (int off = 16; off > 0; off >>= 1) {
        o0 += __shfl_down_sync(0xffffffffu, o0, off);
        o1 += __shfl_down_sync(0xffffffffu, o1, off);
    }
    if ((t & 31) == 0) { redsum[t >> 5][0] = o0; redsum[t >> 5][1] = o1; }
    __syncthreads();
    if (t == 0) {
        float s0 = 0.f, s1 = 0.f;
        #pragma unroll
        for (int w = 0; w < 8; w++) { s0 += redsum[w][0]; s1 += redsum[w][1]; }
        outP[2 * b]     = s0 + bout[0];
        outP[2 * b + 1] = s1 + bout[1];
    }
}

// ---------------- launch ----------------
extern "C" void kernel_launch(void* const* d_in, const int* in_sizes, int n_in,
                              void* d_out, int out_size)
{
    (void)in_sizes; (void)n_in; (void)out_size;
    const float* r_att   = (const float*)d_in[0];
    const float* p_att   = (const float*)d_in[1];
    const float* r_fun   = (const float*)d_in[2];
    const float* p_fun   = (const float*)d_in[3];
    const int*   idx     = (const int*)  d_in[4];
    const float* W_att1  = (const float*)d_in[5];
    const float* b_att1  = (const float*)d_in[6];
    const float* W_att2  = (const float*)d_in[7];
    const float* b_att2  = (const float*)d_in[8];
    const float* W_fun1  = (const float*)d_in[9];
    const float* b_fun1  = (const float*)d_in[10];
    const float* W_fun2  = (const float*)d_in[11];
    const float* b_fun2  = (const float*)d_in[12];
    const float* conv1_w = (const float*)d_in[13];
    const float* conv1_b = (const float*)d_in[14];
    const float* conv2_w = (const float*)d_in[15];
    const float* conv2_b = (const float*)d_in[16];
    const float* W_out   = (const float*)d_in[17];
    const float* b_out   = (const float*)d_in[18];

    float* out   = (float*)d_out;
    float* e     = out;                              // [3512, 512]
    float* outP  = out + (size_t)NT * DCOLS;         // [8192, 2]
    float* flatP = outP + 2 * BATCH;                 // [8192, 8192]

    float *hidden, *part, *Apk;
    cudaGetSymbolAddress((void**)&hidden, g_hidden);
    cudaGetSymbolAddress((void**)&part,   g_part);
    cudaGetSymbolAddress((void**)&Apk,    g_A);

    const int gemmSmem = NSTAGE * STG_BYTES + 16;    // 56848
    cudaFuncSetAttribute(gemm_tf32, cudaFuncAttributeMaxDynamicSharedMemorySize, gemmSmem);

    const int mT = (NT + 127) / 128;                 // 28

    // ===== ATT branch =====
    {
        size_t n4 = (size_t)M_PAD * (KP_ATT / 4);
        pack_A<<<(unsigned)((n4 + 255) / 256), 256>>>(r_att, p_att, N_RNA, SZ_R, KP_ATT, Apk);
        gemm_tf32<<<dim3(H_ATT / 128, mT, 1), 256, gemmSmem>>>(
            Apk, KP_ATT, NT, W_att1, H_ATT, SZ_R, KP_ATT, b_att1, hidden, 0);
        gemm_tf32<<<dim3(2, mT, SPLITS2), 256, gemmSmem>>>(
            hidden, H_ATT, NT, W_att2, 256, H_ATT, H_ATT / SPLITS2, nullptr, part, 1);
        gemm2_reduce<<<(NT * 256 + 255) / 256, 256>>>(part, b_att2, e, NT, 0);
    }
    // ===== FUN branch =====
    {
        size_t n4 = (size_t)M_PAD * (KP_FUN / 4);
        pack_A<<<(unsigned)((n4 + 255) / 256), 256>>>(r_fun, p_fun, N_RNA, FUN_IN, KP_FUN, Apk);
        gemm_tf32<<<dim3(H_FUN / 128, mT, 1), 256, gemmSmem>>>(
            Apk, KP_FUN, NT, W_fun1, H_FUN, FUN_IN, KP_FUN, b_fun1, hidden, 0);
        gemm_tf32<<<dim3(2, mT, SPLITS2), 256, gemmSmem>>>(
            hidden, H_FUN, NT, W_fun2, 256, H_FUN, H_FUN / SPLITS2, nullptr, part, 1);
        gemm2_reduce<<<(NT * 256 + 255) / 256, 256>>>(part, b_fun2, e, NT, 256);
    }

    // fused conv stack
    const int convSmem = 25000 * 4;                  // 100000 B
    cudaFuncSetAttribute(conv_fused, cudaFuncAttributeMaxDynamicSharedMemorySize, convSmem);
    conv_fused<<<BATCH, 256, convSmem>>>(e, idx, conv1_w, conv1_b, conv2_w, conv2_b,
                                         W_out, b_out, outP, flatP);
}

// round 9
// speedup vs baseline: 2.4585x; 1.1025x over previous
#include <cuda_runtime.h>
#include <cstdint>

// ---------------- problem constants ----------------
#define N_RNA   2000
#define N_PROT  1512
#define NT      3512
#define SZ_R    3000
#define FUN_IN  5603
#define H_ATT   2048
#define H_FUN   4096
#define DCOLS   512
#define BATCH   8192
#define PROTEIN 1512
#define FLATSZ  8192
#define SPLITS2 8

#define M_PAD   3584            // 28 * 128
#define KP_ATT  3008            // 16-float multiple >= 3000
#define KP_FUN  5616            // 16-float multiple >= 5603

// scratch
__device__ float g_hidden[NT * (size_t)H_FUN];                 // 57.5 MB
__device__ float g_part[SPLITS2 * (size_t)NT * 256];           // 28.8 MB
__device__ float g_A[(size_t)M_PAD * KP_FUN];                  // 80.5 MB

// ---------------- helpers ----------------
__device__ __forceinline__ uint32_t smem_u32(const void* p) {
    uint32_t a;
    asm("{ .reg .u64 t; cvta.to.shared.u64 t, %1; cvt.u32.u64 %0, t; }" : "=r"(a) : "l"(p));
    return a;
}
__device__ __forceinline__ void mma_tf32(float c[4],
                                         const uint32_t a[4], const uint32_t b[2]) {
    asm volatile(
        "mma.sync.aligned.m16n8k8.row.col.f32.tf32.tf32.f32 "
        "{%0,%1,%2,%3},{%4,%5,%6,%7},{%8,%9},{%0,%1,%2,%3};"
        : "+f"(c[0]), "+f"(c[1]), "+f"(c[2]), "+f"(c[3])
        : "r"(a[0]), "r"(a[1]), "r"(a[2]), "r"(a[3]), "r"(b[0]), "r"(b[1]));
}
#define CPA16(dst, src) \
    asm volatile("cp.async.ca.shared.global [%0], [%1], 16;" :: "r"(dst), "l"(src))
#define CPA16Z(dst, src, sz) \
    asm volatile("cp.async.ca.shared.global [%0], [%1], 16, %2;" \
                 :: "r"(dst), "l"(src), "r"(sz))
#define CP_COMMIT() asm volatile("cp.async.commit_group;" ::: "memory")

// packed f32x2 (Blackwell): FFMA2 path, PTX-only
#define PK2(d, lo, hi) \
    asm("mov.b64 %0, {%1, %2};" : "=l"(d) : "f"(lo), "f"(hi))
#define UPK2(lo, hi, s) \
    asm("mov.b64 {%0, %1}, %2;" : "=f"(lo), "=f"(hi) : "l"(s))
#define FMA2(d, a, b) \
    asm("fma.rn.f32x2 %0, %1, %2, %0;" : "+l"(d) : "l"(a), "l"(b))

// smem per stage: A [128][20] floats (10240 B) + B [16][136] floats (8704 B)
#define KT        16
#define ALD       20
#define BLD       136
#define A_BYTES   10240
#define STG_BYTES 18944
#define NSTAGE    3

// =====================================================================
// tf32 mma.sync GEMM — validated compute core, cp.async staging.
// (unchanged from rounds 7/8)
// =====================================================================
__global__ __launch_bounds__(256, 2)
void gemm_tf32(const float* __restrict__ A, int lda, int Mreal,
               const float* __restrict__ B, int N, int Kreal, int kLen,
               const float* __restrict__ bias, float* __restrict__ Cout,
               int mode)
{
    extern __shared__ __align__(16) char smemRaw[];
    uint32_t* smemW = (uint32_t*)smemRaw;
    const uint32_t smB = smem_u32(smemRaw);

    const int tid  = threadIdx.x;
    const int lane = tid & 31;
    const int wid  = tid >> 5;
    const int mWarp = (wid >> 2) * 64;
    const int nWarp = (wid & 3) * 32;
    const int rowTile = blockIdx.y * 128;
    const int colBase = blockIdx.x * 128;

    const int kBeg = blockIdx.z * kLen;
    const int nk   = (min(kBeg + kLen, Kreal) - kBeg + KT - 1) / KT;

    const int aRow  = tid >> 1;
    const int aHalf = (tid & 1) * 8;
    int gRow = rowTile + aRow; if (gRow >= Mreal) gRow = Mreal - 1;
    const float* Arow = A + (size_t)gRow * lda;
    const uint32_t aDst = (uint32_t)(aRow * ALD + aHalf) * 4u;

    const int bk0 = tid >> 5;
    const int bn4 = lane * 4;

    float acc[4][4][4] = {};

    auto stage = [&](int buf, int k0) {
        uint32_t base = smB + (uint32_t)buf * STG_BYTES;
        CPA16(base + aDst,       Arow + k0 + aHalf);
        CPA16(base + aDst + 16u, Arow + k0 + aHalf + 4);
        #pragma unroll
        for (int j = 0; j < 2; j++) {
            int kk = bk0 + j * 8;
            int gk = k0 + kk;
            uint32_t sz = (gk < Kreal) ? 16u : 0u;
            int gkc = (gk < Kreal) ? gk : Kreal - 1;
            CPA16Z(base + A_BYTES + (uint32_t)(kk * BLD + bn4) * 4u,
                   B + (size_t)gkc * N + colBase + bn4, sz);
        }
    };

    stage(0, kBeg); CP_COMMIT();
    if (nk > 1) { stage(1, kBeg + KT); CP_COMMIT(); }

    for (int t = 0; t < nk; t++) {
        if (t + 1 < nk) asm volatile("cp.async.wait_group 1;" ::: "memory");
        else            asm volatile("cp.async.wait_group 0;" ::: "memory");
        __syncthreads();

        const uint32_t* As = smemW + (size_t)(t % NSTAGE) * (STG_BYTES / 4);
        const uint32_t* Bs = As + (A_BYTES / 4);

        #pragma unroll
        for (int ks = 0; ks < 2; ks++) {
            const int k8 = ks * 8;
            uint32_t af[4][4], bf[4][2];
            #pragma unroll
            for (int mi = 0; mi < 4; mi++) {
                int m0 = mWarp + mi * 16 + (lane >> 2);
                const uint32_t* ap = &As[m0 * ALD + k8 + (lane & 3)];
                af[mi][0] = ap[0];
                af[mi][1] = ap[8 * ALD];
                af[mi][2] = ap[4];
                af[mi][3] = ap[8 * ALD + 4];
            }
            #pragma unroll
            for (int ni = 0; ni < 4; ni++) {
                int n0 = nWarp + ni * 8 + (lane >> 2);
                const uint32_t* bp = &Bs[(k8 + (lane & 3)) * BLD + n0];
                bf[ni][0] = bp[0];
                bf[ni][1] = bp[4 * BLD];
            }
            #pragma unroll
            for (int mi = 0; mi < 4; mi++)
                #pragma unroll
                for (int ni = 0; ni < 4; ni++)
                    mma_tf32(acc[mi][ni], af[mi], bf[ni]);
        }
        __syncthreads();
        if (t + 2 < nk) {
            stage((t + 2) % NSTAGE, kBeg + (t + 2) * KT);
            CP_COMMIT();
        }
    }

    float* outBase = (mode == 1) ? (Cout + (size_t)blockIdx.z * Mreal * N) : Cout;
    #pragma unroll
    for (int mi = 0; mi < 4; mi++) {
        int r0 = rowTile + mWarp + mi * 16 + (lane >> 2);
        #pragma unroll
        for (int ni = 0; ni < 4; ni++) {
            int c = colBase + nWarp + ni * 8 + 2 * (lane & 3);
            float v0 = acc[mi][ni][0], v1 = acc[mi][ni][1];
            float v2 = acc[mi][ni][2], v3 = acc[mi][ni][3];
            if (mode == 0) {
                float2 bb = *(const float2*)(bias + c);
                v0 += bb.x; v1 += bb.y; v2 += bb.x; v3 += bb.y;
                v0 = 0.5f * v0 * (1.f + erff(v0 * 0.70710678118654752f));
                v1 = 0.5f * v1 * (1.f + erff(v1 * 0.70710678118654752f));
                v2 = 0.5f * v2 * (1.f + erff(v2 * 0.70710678118654752f));
                v3 = 0.5f * v3 * (1.f + erff(v3 * 0.70710678118654752f));
            }
            if (r0 < Mreal)     *(float2*)(outBase + (size_t)r0 * N + c)       = make_float2(v0, v1);
            if (r0 + 8 < Mreal) *(float2*)(outBase + (size_t)(r0 + 8) * N + c) = make_float2(v2, v3);
        }
    }
}

// ---------------- pack A (unchanged) ----------------
__global__ __launch_bounds__(256)
void pack_A(const float* __restrict__ A0, const float* __restrict__ A1,
            int split, int Kreal, int Kpad, float* __restrict__ dst)
{
    size_t i = (size_t)blockIdx.x * 256 + threadIdx.x;
    size_t tot = (size_t)M_PAD * (Kpad >> 2);
    if (i >= tot) return;
    int r = (int)(i / (Kpad >> 2));
    int k = (int)(i % (Kpad >> 2)) * 4;
    float4 v = make_float4(0.f, 0.f, 0.f, 0.f);
    if (r < NT) {
        const float* src = (r < split) ? (A0 + (size_t)r * Kreal)
                                       : (A1 + (size_t)(r - split) * Kreal);
        if (k     < Kreal) v.x = __ldg(src + k);
        if (k + 1 < Kreal) v.y = __ldg(src + k + 1);
        if (k + 2 < Kreal) v.z = __ldg(src + k + 2);
        if (k + 3 < Kreal) v.w = __ldg(src + k + 3);
    }
    *(float4*)(dst + (size_t)r * Kpad + k) = v;
}

// ---------------- split-K reduce + sigmoid ----------------
__global__ __launch_bounds__(256)
void gemm2_reduce(const float* __restrict__ part, const float* __restrict__ bias,
                  float* __restrict__ E, int M, int colOff)
{
    int idx = blockIdx.x * 256 + threadIdx.x;
    if (idx >= M * 256) return;
    int r = idx >> 8, c = idx & 255;
    float s = 0.f;
    #pragma unroll
    for (int z = 0; z < SPLITS2; z++)
        s += part[((size_t)z * M + r) * 256 + c];
    s += bias[c];
    s = 1.f / (1.f + __expf(-s));
    E[(size_t)r * DCOLS + colOff + c] = s;
}

// ---------------- fused conv stack: FFMA2 conv2, two-pass weight dup ----------------
// smem = 17320 floats = 69280 B  -> 3 CTAs/SM
__global__ __launch_bounds__(256)
void conv_fused(const float* __restrict__ e, const int* __restrict__ idx,
                const float* __restrict__ w1, const float* __restrict__ b1,
                const float* __restrict__ w2, const float* __restrict__ b2,
                const float* __restrict__ Wout, const float* __restrict__ bout,
                float* __restrict__ outP, float* __restrict__ flatP)
{
    extern __shared__ float sm[];
    float* xs  = sm;             // 1032
    float* p1s = xs + 1032;      // 8320
    float* w1s = p1s + 8320;     // 240
    float* b1s = w1s + 240;      // 16
    float* b2s = b1s + 16;       // 32
    float* wdup = b2s + 32;      // 7680 (16 channels' duplicated [w,w] pairs, reused)
    __shared__ float redsum[8][2];

    int t = threadIdx.x;
    int b = blockIdx.x;

    for (int i = t; i < 240; i += 256)  w1s[i] = w1[i];
    if (t < 16) b1s[t] = b1[t];
    if (t < 32) b2s[t] = b2[t];

    int id  = idx[b];
    int rno = id / PROTEIN;
    int pno = id - rno * PROTEIN;
    const float* row0 = e + (size_t)rno * DCOLS;
    const float* row1 = e + (size_t)(N_RNA + pno) * DCOLS;
    for (int i = t; i < 1032; i += 256) {
        int rr = (i >= 516), c = i - rr * 516;
        float v = 0.f;
        if (c >= 2 && c < 514) v = (rr == 0 ? row0 : row1)[c - 2];
        xs[i] = v;
    }
    if (t < 128) {
        int rr = t >> 2, j = t & 3;
        int col = (j < 2) ? j : 256 + j;
        p1s[rr * 260 + col] = 0.f;
    }
    __syncthreads();

    // conv1 + leaky + avgpool (unchanged, validated)
    for (int li = t; li < 8192; li += 256) {
        int c = li >> 9, ph = (li >> 8) & 1, pw = li & 255;
        const float* wc = &w1s[c * 15];
        float bb = b1s[c];
        float s = 0.f;
        #pragma unroll
        for (int d = 0; d < 4; d++) {
            int h = 2 * ph + (d >> 1);
            int w = 2 * pw + (d & 1);
            float acc = bb;
            #pragma unroll
            for (int kh = 0; kh < 3; kh++) {
                int r = h + kh - 2;
                if (r >= 0 && r < 2) {
                    #pragma unroll
                    for (int kw = 0; kw < 5; kw++)
                        acc += wc[kh * 5 + kw] * xs[r * 516 + w + kw];
                }
            }
            s += (acc >= 0.f) ? acc : 0.01f * acc;
        }
        p1s[(c * 2 + ph) * 260 + pw + 2] = 0.25f * s;
    }

    // conv2 + leaky + maxpool + tanh + out-GEMM — FFMA2, two 16-channel passes
    int ph = t >> 7;        // uniform per warp
    int pw = t & 127;
    float o0 = 0.f, o1 = 0.f;

    for (int pass = 0; pass < 2; pass++) {
        __syncthreads();      // previous consumers of wdup done (also covers conv1 sync)
        for (int i = t; i < 3840; i += 256) {
            float w = w2[pass * 3840 + i];
            ((float2*)wdup)[i] = make_float2(w, w);
        }
        __syncthreads();

        for (int cb = 0; cb < 16; cb += 8) {
            unsigned long long acc01[8], acc23[8];
            #pragma unroll
            for (int j = 0; j < 8; j++) {
                float bb = b2s[pass * 16 + cb + j];
                PK2(acc01[j], bb, bb);
                acc23[j] = acc01[j];
            }
            for (int ci = 0; ci < 16; ci++) {
                const float2* q0 = (const float2*)&p1s[(ci * 2 + 0) * 260 + 2 * pw];
                const float2* q1 = (const float2*)&p1s[(ci * 2 + 1) * 260 + 2 * pw];
                float2 u0 = q0[0], u1 = q0[1], u2 = q0[2];
                float2 v0 = q1[0], v1 = q1[1], v2 = q1[2];
                unsigned long long p0[5], p1p[5];
                PK2(p0[0],  u0.x, u0.y); PK2(p0[1],  u0.y, u1.x); PK2(p0[2],  u1.x, u1.y);
                PK2(p0[3],  u1.y, u2.x); PK2(p0[4],  u2.x, u2.y);
                PK2(p1p[0], v0.x, v0.y); PK2(p1p[1], v0.y, v1.x); PK2(p1p[2], v1.x, v1.y);
                PK2(p1p[3], v1.y, v2.x); PK2(p1p[4], v2.x, v2.y);
                #pragma unroll
                for (int j = 0; j < 8; j++) {
                    const unsigned long long* wd =
                        (const unsigned long long*)&wdup[((cb + j) * 240 + ci * 15) * 2];
                    if (ph == 0) {
                        #pragma unroll
                        for (int kw = 0; kw < 5; kw++) {
                            unsigned long long wA = wd[10 + kw], wB = wd[5 + kw];
                            FMA2(acc01[j], wA, p0[kw]);
                            FMA2(acc23[j], wB, p0[kw]);
                            FMA2(acc23[j], wA, p1p[kw]);
                        }
                    } else {
                        #pragma unroll
                        for (int kw = 0; kw < 5; kw++) {
                            unsigned long long wA = wd[kw], wB = wd[5 + kw];
                            FMA2(acc01[j], wA, p0[kw]);
                            FMA2(acc01[j], wB, p1p[kw]);
                            FMA2(acc23[j], wA, p1p[kw]);
                        }
                    }
                }
            }
            #pragma unroll
            for (int j = 0; j < 8; j++) {
                float a0, a1, a2, a3;
                UPK2(a0, a1, acc01[j]);
                UPK2(a2, a3, acc23[j]);
                a0 = (a0 >= 0.f) ? a0 : 0.01f * a0;
                a1 = (a1 >= 0.f) ? a1 : 0.01f * a1;
                a2 = (a2 >= 0.f) ? a2 : 0.01f * a2;
                a3 = (a3 >= 0.f) ? a3 : 0.01f * a3;
                float m  = fmaxf(fmaxf(a0, a1), fmaxf(a2, a3));
                float tv = tanhf(m);
                int fi = (pass * 16 + cb + j) * 256 + ph * 128 + pw;
                flatP[(size_t)b * FLATSZ + fi] = tv;
                o0 += tv * Wout[2 * fi];
                o1 += tv * Wout[2 * fi + 1];
            }
        }
    }

    #pragma unroll
    for (int off = 16; off > 0; off >>= 1) {
        o0 += __shfl_down_sync(0xffffffffu, o0, off);
        o1 += __shfl_down_sync(0xffffffffu, o1, off);
    }
    if ((t & 31) == 0) { redsum[t >> 5][0] = o0; redsum[t >> 5][1] = o1; }
    __syncthreads();
    if (t == 0) {
        float s0 = 0.f, s1 = 0.f;
        #pragma unroll
        for (int w = 0; w < 8; w++) { s0 += redsum[w][0]; s1 += redsum[w][1]; }
        outP[2 * b]     = s0 + bout[0];
        outP[2 * b + 1] = s1 + bout[1];
    }
}

// ---------------- launch ----------------
extern "C" void kernel_launch(void* const* d_in, const int* in_sizes, int n_in,
                              void* d_out, int out_size)
{
    (void)in_sizes; (void)n_in; (void)out_size;
    const float* r_att   = (const float*)d_in[0];
    const float* p_att   = (const float*)d_in[1];
    const float* r_fun   = (const float*)d_in[2];
    const float* p_fun   = (const float*)d_in[3];
    const int*   idx     = (const int*)  d_in[4];
    const float* W_att1  = (const float*)d_in[5];
    const float* b_att1  = (const float*)d_in[6];
    const float* W_att2  = (const float*)d_in[7];
    const float* b_att2  = (const float*)d_in[8];
    const float* W_fun1  = (const float*)d_in[9];
    const float* b_fun1  = (const float*)d_in[10];
    const float* W_fun2  = (const float*)d_in[11];
    const float* b_fun2  = (const float*)d_in[12];
    const float* conv1_w = (const float*)d_in[13];
    const float* conv1_b = (const float*)d_in[14];
    const float* conv2_w = (const float*)d_in[15];
    const float* conv2_b = (const float*)d_in[16];
    const float* W_out   = (const float*)d_in[17];
    const float* b_out   = (const float*)d_in[18];

    float* out   = (float*)d_out;
    float* e     = out;                              // [3512, 512]
    float* outP  = out + (size_t)NT * DCOLS;         // [8192, 2]
    float* flatP = outP + 2 * BATCH;                 // [8192, 8192]

    float *hidden, *part, *Apk;
    cudaGetSymbolAddress((void**)&hidden, g_hidden);
    cudaGetSymbolAddress((void**)&part,   g_part);
    cudaGetSymbolAddress((void**)&Apk,    g_A);

    const int gemmSmem = NSTAGE * STG_BYTES + 16;    // 56848
    cudaFuncSetAttribute(gemm_tf32, cudaFuncAttributeMaxDynamicSharedMemorySize, gemmSmem);

    const int mT = (NT + 127) / 128;                 // 28

    // ===== ATT branch =====
    {
        size_t n4 = (size_t)M_PAD * (KP_ATT / 4);
        pack_A<<<(unsigned)((n4 + 255) / 256), 256>>>(r_att, p_att, N_RNA, SZ_R, KP_ATT, Apk);
        gemm_tf32<<<dim3(H_ATT / 128, mT, 1), 256, gemmSmem>>>(
            Apk, KP_ATT, NT, W_att1, H_ATT, SZ_R, KP_ATT, b_att1, hidden, 0);
        gemm_tf32<<<dim3(2, mT, SPLITS2), 256, gemmSmem>>>(
            hidden, H_ATT, NT, W_att2, 256, H_ATT, H_ATT / SPLITS2, nullptr, part, 1);
        gemm2_reduce<<<(NT * 256 + 255) / 256, 256>>>(part, b_att2, e, NT, 0);
    }
    // ===== FUN branch =====
    {
        size_t n4 = (size_t)M_PAD * (KP_FUN / 4);
        pack_A<<<(unsigned)((n4 + 255) / 256), 256>>>(r_fun, p_fun, N_RNA, FUN_IN, KP_FUN, Apk);
        gemm_tf32<<<dim3(H_FUN / 128, mT, 1), 256, gemmSmem>>>(
            Apk, KP_FUN, NT, W_fun1, H_FUN, FUN_IN, KP_FUN, b_fun1, hidden, 0);
        gemm_tf32<<<dim3(2, mT, SPLITS2), 256, gemmSmem>>>(
            hidden, H_FUN, NT, W_fun2, 256, H_FUN, H_FUN / SPLITS2, nullptr, part, 1);
        gemm2_reduce<<<(NT * 256 + 255) / 256, 256>>>(part, b_fun2, e, NT, 256);
    }

    // fused conv stack — smem back to 69280 B => 3 CTAs/SM
    const int convSmem = 17320 * 4;
    cudaFuncSetAttribute(conv_fused, cudaFuncAttributeMaxDynamicSharedMemorySize, convSmem);
    conv_fused<<<BATCH, 256, convSmem>>>(e, idx, conv1_w, conv1_b, conv2_w, conv2_b,
                                         W_out, b_out, outP, flatP);
}

// round 10
// speedup vs baseline: 2.9354x; 1.1940x over previous
#include <cuda_runtime.h>
#include <cuda_fp16.h>
#include <cstdint>

// ---------------- problem constants ----------------
#define N_RNA   2000
#define N_PROT  1512
#define NT      3512
#define SZ_R    3000
#define FUN_IN  5603
#define H_ATT   2048
#define H_FUN   4096
#define DCOLS   512
#define BATCH   8192
#define PROTEIN 1512
#define FLATSZ  8192
#define SPLITS2 8

#define M_PAD   3584            // 28 * 128
#define KP_ATT  3008            // 32-float multiple >= 3000
#define KP_FUN  5632            // 32-float multiple >= 5603

// scratch (half precision operand stores + f32 partials)
__device__ __half g_Ah[(size_t)M_PAD * KP_FUN];        // 40.4 MB
__device__ __half g_Bth[(size_t)H_FUN * KP_FUN];       // 46.1 MB
__device__ __half g_B2h[(size_t)256 * H_FUN];          // 2 MB
__device__ __half g_hidden_h[(size_t)NT * H_FUN];      // 28.8 MB
__device__ float  g_part[SPLITS2 * (size_t)NT * 256];  // 28.8 MB

// ---------------- helpers ----------------
__device__ __forceinline__ uint32_t smem_u32(const void* p) {
    uint32_t a;
    asm("{ .reg .u64 t; cvta.to.shared.u64 t, %1; cvt.u32.u64 %0, t; }" : "=r"(a) : "l"(p));
    return a;
}
__device__ __forceinline__ void mma_f16(float c[4],
                                        const uint32_t a[4], const uint32_t b[2]) {
    asm volatile(
        "mma.sync.aligned.m16n8k16.row.col.f32.f16.f16.f32 "
        "{%0,%1,%2,%3},{%4,%5,%6,%7},{%8,%9},{%0,%1,%2,%3};"
        : "+f"(c[0]), "+f"(c[1]), "+f"(c[2]), "+f"(c[3])
        : "r"(a[0]), "r"(a[1]), "r"(a[2]), "r"(a[3]), "r"(b[0]), "r"(b[1]));
}
#define CPA16(dst, src) \
    asm volatile("cp.async.ca.shared.global [%0], [%1], 16;" :: "r"(dst), "l"(src))
#define CP_COMMIT() asm volatile("cp.async.commit_group;" ::: "memory")

// packed f32x2 (Blackwell): FFMA2 path, PTX-only  (conv2, validated R8/R9)
#define PK2(d, lo, hi) \
    asm("mov.b64 %0, {%1, %2};" : "=l"(d) : "f"(lo), "f"(hi))
#define UPK2(lo, hi, s) \
    asm("mov.b64 {%0, %1}, %2;" : "=f"(lo), "=f"(hi) : "l"(s))
#define FMA2(d, a, b) \
    asm("fma.rn.f32x2 %0, %1, %2, %0;" : "+l"(d) : "l"(a), "l"(b))

// smem per stage: A [128 rows][80B] (10240) + B [128 n][80B] (10240)
#define KT        32            // K (halves==elements) per staged iter
#define A_BYTES   10240
#define STG_BYTES 20480
#define NSTAGE    3

// =====================================================================
// fp16 mma.sync GEMM (m16n8k16), tile 128x128, KT=32, 3-stage cp.async.
//   A half [*, lda] K-major; Bt half [N][ldb] K-major (pre-transposed).
//   Both zero-padded in K to multiples of 32 -> unconditional 16B cp.async.
//   mode 0: CoutH[r][n] = half(gelu(acc + bias[n]))   (grid.z == 1)
//   mode 1: CoutF[z][r][n] = acc over K chunk z       (split-K, kLen | 32)
// Fragment word-indexing identical to the validated tf32 core (20-word rows).
// =====================================================================
__global__ __launch_bounds__(256, 2)
void gemm_f16(const __half* __restrict__ A, int lda, int Mreal,
              const __half* __restrict__ Bt, int ldb, int N, int kLen,
              const float* __restrict__ bias, __half* __restrict__ CoutH,
              float* __restrict__ CoutF, int mode)
{
    extern __shared__ __align__(16) char smemRaw[];
    uint32_t* smemW = (uint32_t*)smemRaw;
    const uint32_t smB = smem_u32(smemRaw);

    const int tid  = threadIdx.x;
    const int lane = tid & 31;
    const int wid  = tid >> 5;
    const int mWarp = (wid >> 2) * 64;
    const int nWarp = (wid & 3) * 32;
    const int rowTile = blockIdx.y * 128;
    const int colBase = blockIdx.x * 128;

    const int kBeg = blockIdx.z * kLen;
    const int nk   = kLen >> 5;                    // kLen multiple of 32 by construction

    // staging coords: thread -> one A row and one B row, two 16B chunks each
    const int sRow = tid >> 1;                     // 0..127
    const int cBase = (tid & 1) * 2;               // chunks {0,1} or {2,3}
    int gRow = rowTile + sRow; if (gRow >= Mreal) gRow = Mreal - 1;
    const __half* Arow = A + (size_t)gRow * lda;
    const __half* Brow = Bt + (size_t)(colBase + sRow) * ldb;
    const uint32_t sOff = (uint32_t)sRow * 80u + (uint32_t)cBase * 16u;

    float acc[4][4][4] = {};

    auto stage = [&](int buf, int k0) {
        uint32_t base = smB + (uint32_t)buf * STG_BYTES;
        CPA16(base + sOff,                 Arow + k0 + cBase * 8);
        CPA16(base + sOff + 16u,           Arow + k0 + cBase * 8 + 8);
        CPA16(base + A_BYTES + sOff,       Brow + k0 + cBase * 8);
        CPA16(base + A_BYTES + sOff + 16u, Brow + k0 + cBase * 8 + 8);
    };

    stage(0, kBeg); CP_COMMIT();
    if (nk > 1) { stage(1, kBeg + KT); CP_COMMIT(); }

    for (int t = 0; t < nk; t++) {
        if (t + 1 < nk) asm volatile("cp.async.wait_group 1;" ::: "memory");
        else            asm volatile("cp.async.wait_group 0;" ::: "memory");
        __syncthreads();

        const uint32_t* As = smemW + (size_t)(t % NSTAGE) * (STG_BYTES / 4);
        const uint32_t* Bs = As + (A_BYTES / 4);

        #pragma unroll
        for (int ks = 0; ks < 2; ks++) {          // two k16 slabs per KT=32
            const int k8 = ks * 8;                 // word offset of slab
            uint32_t af[4][4], bf[4][2];
            #pragma unroll
            for (int mi = 0; mi < 4; mi++) {
                int m0 = mWarp + mi * 16 + (lane >> 2);
                const uint32_t* ap = &As[m0 * 20 + k8 + (lane & 3)];
                af[mi][0] = ap[0];
                af[mi][1] = ap[8 * 20];
                af[mi][2] = ap[4];
                af[mi][3] = ap[8 * 20 + 4];
            }
            #pragma unroll
            for (int ni = 0; ni < 4; ni++) {
                int n0 = nWarp + ni * 8 + (lane >> 2);
                const uint32_t* bp = &Bs[n0 * 20 + k8 + (lane & 3)];
                bf[ni][0] = bp[0];
                bf[ni][1] = bp[4];
            }
            #pragma unroll
            for (int mi = 0; mi < 4; mi++)
                #pragma unroll
                for (int ni = 0; ni < 4; ni++)
                    mma_f16(acc[mi][ni], af[mi], bf[ni]);
        }
        // no second __syncthreads: buffer (t+2)%3 was last read at iter t-1,
        // already fenced by this iteration's top barrier.
        if (t + 2 < nk) {
            stage((t + 2) % NSTAGE, kBeg + (t + 2) * KT);
            CP_COMMIT();
        }
    }

    // ---- epilogue (C layout identical to tf32 core) ----
    #pragma unroll
    for (int mi = 0; mi < 4; mi++) {
        int r0 = rowTile + mWarp + mi * 16 + (lane >> 2);
        #pragma unroll
        for (int ni = 0; ni < 4; ni++) {
            int c = colBase + nWarp + ni * 8 + 2 * (lane & 3);
            float v0 = acc[mi][ni][0], v1 = acc[mi][ni][1];
            float v2 = acc[mi][ni][2], v3 = acc[mi][ni][3];
            if (mode == 0) {
                float2 bb = *(const float2*)(bias + c);
                v0 += bb.x; v1 += bb.y; v2 += bb.x; v3 += bb.y;
                v0 = 0.5f * v0 * (1.f + erff(v0 * 0.70710678118654752f));
                v1 = 0.5f * v1 * (1.f + erff(v1 * 0.70710678118654752f));
                v2 = 0.5f * v2 * (1.f + erff(v2 * 0.70710678118654752f));
                v3 = 0.5f * v3 * (1.f + erff(v3 * 0.70710678118654752f));
                if (r0 < Mreal)
                    *(__half2*)(CoutH + (size_t)r0 * N + c) = __floats2half2_rn(v0, v1);
                if (r0 + 8 < Mreal)
                    *(__half2*)(CoutH + (size_t)(r0 + 8) * N + c) = __floats2half2_rn(v2, v3);
            } else {
                float* outF = CoutF + (size_t)blockIdx.z * Mreal * N;
                if (r0 < Mreal)
                    *(float2*)(outF + (size_t)r0 * N + c) = make_float2(v0, v1);
                if (r0 + 8 < Mreal)
                    *(float2*)(outF + (size_t)(r0 + 8) * N + c) = make_float2(v2, v3);
            }
        }
    }
}

// ---------------- pack A: concat rows -> half [M_PAD][Kpad], zero-padded ------
__global__ __launch_bounds__(256)
void pack_A_h(const float* __restrict__ A0, const float* __restrict__ A1,
              int split, int Kreal, int Kpad, __half* __restrict__ dst)
{
    size_t i = (size_t)blockIdx.x * 256 + threadIdx.x;
    size_t tot = (size_t)M_PAD * (Kpad >> 2);
    if (i >= tot) return;
    int r = (int)(i / (Kpad >> 2));
    int k = (int)(i % (Kpad >> 2)) * 4;
    float v0 = 0.f, v1 = 0.f, v2 = 0.f, v3 = 0.f;
    if (r < NT) {
        const float* src = (r < split) ? (A0 + (size_t)r * Kreal)
                                       : (A1 + (size_t)(r - split) * Kreal);
        if (k     < Kreal) v0 = __ldg(src + k);
        if (k + 1 < Kreal) v1 = __ldg(src + k + 1);
        if (k + 2 < Kreal) v2 = __ldg(src + k + 2);
        if (k + 3 < Kreal) v3 = __ldg(src + k + 3);
    }
    __half2* d = (__half2*)(dst + (size_t)r * Kpad + k);
    d[0] = __floats2half2_rn(v0, v1);
    d[1] = __floats2half2_rn(v2, v3);
}

// ---------------- transpose+convert B [Kreal][N] f32 -> [N][Kpad] half --------
__global__ void convertB(const float* __restrict__ B, __half* __restrict__ Bt,
                         int Kreal, int Kpad, int N)
{
    __shared__ float tile[32][33];
    int n0 = blockIdx.x * 32, k0 = blockIdx.y * 32;
    int tx = threadIdx.x, ty = threadIdx.y;
    #pragma unroll
    for (int j = 0; j < 4; j++) {
        int k = k0 + ty + j * 8;
        tile[ty + j * 8][tx] = (k < Kreal) ? B[(size_t)k * N + n0 + tx] : 0.f;
    }
    __syncthreads();
    #pragma unroll
    for (int j = 0; j < 4; j++) {
        int n = n0 + ty + j * 8;
        Bt[(size_t)n * Kpad + k0 + tx] = __float2half_rn(tile[tx][ty + j * 8]);
    }
}

// ---------------- split-K reduce + sigmoid (unchanged) ----------------
__global__ __launch_bounds__(256)
void gemm2_reduce(const float* __restrict__ part, const float* __restrict__ bias,
                  float* __restrict__ E, int M, int colOff)
{
    int idx = blockIdx.x * 256 + threadIdx.x;
    if (idx >= M * 256) return;
    int r = idx >> 8, c = idx & 255;
    float s = 0.f;
    #pragma unroll
    for (int z = 0; z < SPLITS2; z++)
        s += part[((size_t)z * M + r) * 256 + c];
    s += bias[c];
    s = 1.f / (1.f + __expf(-s));
    E[(size_t)r * DCOLS + colOff + c] = s;
}

// ---------------- fused conv stack (unchanged, validated R9) ----------------
__global__ __launch_bounds__(256)
void conv_fused(const float* __restrict__ e, const int* __restrict__ idx,
                const float* __restrict__ w1, const float* __restrict__ b1,
                const float* __restrict__ w2, const float* __restrict__ b2,
                const float* __restrict__ Wout, const float* __restrict__ bout,
                float* __restrict__ outP, float* __restrict__ flatP)
{
    extern __shared__ float sm[];
    float* xs  = sm;             // 1032
    float* p1s = xs + 1032;      // 8320
    float* w1s = p1s + 8320;     // 240
    float* b1s = w1s + 240;      // 16
    float* b2s = b1s + 16;       // 32
    float* wdup = b2s + 32;      // 7680
    __shared__ float redsum[8][2];

    int t = threadIdx.x;
    int b = blockIdx.x;

    for (int i = t; i < 240; i += 256)  w1s[i] = w1[i];
    if (t < 16) b1s[t] = b1[t];
    if (t < 32) b2s[t] = b2[t];

    int id  = idx[b];
    int rno = id / PROTEIN;
    int pno = id - rno * PROTEIN;
    const float* row0 = e + (size_t)rno * DCOLS;
    const float* row1 = e + (size_t)(N_RNA + pno) * DCOLS;
    for (int i = t; i < 1032; i += 256) {
        int rr = (i >= 516), c = i - rr * 516;
        float v = 0.f;
        if (c >= 2 && c < 514) v = (rr == 0 ? row0 : row1)[c - 2];
        xs[i] = v;
    }
    if (t < 128) {
        int rr = t >> 2, j = t & 3;
        int col = (j < 2) ? j : 256 + j;
        p1s[rr * 260 + col] = 0.f;
    }
    __syncthreads();

    for (int li = t; li < 8192; li += 256) {
        int c = li >> 9, ph = (li >> 8) & 1, pw = li & 255;
        const float* wc = &w1s[c * 15];
        float bb = b1s[c];
        float s = 0.f;
        #pragma unroll
        for (int d = 0; d < 4; d++) {
            int h = 2 * ph + (d >> 1);
            int w = 2 * pw + (d & 1);
            float acc = bb;
            #pragma unroll
            for (int kh = 0; kh < 3; kh++) {
                int r = h + kh - 2;
                if (r >= 0 && r < 2) {
                    #pragma unroll
                    for (int kw = 0; kw < 5; kw++)
                        acc += wc[kh * 5 + kw] * xs[r * 516 + w + kw];
                }
            }
            s += (acc >= 0.f) ? acc : 0.01f * acc;
        }
        p1s[(c * 2 + ph) * 260 + pw + 2] = 0.25f * s;
    }

    int ph = t >> 7;
    int pw = t & 127;
    float o0 = 0.f, o1 = 0.f;

    for (int pass = 0; pass < 2; pass++) {
        __syncthreads();
        for (int i = t; i < 3840; i += 256) {
            float w = w2[pass * 3840 + i];
            ((float2*)wdup)[i] = make_float2(w, w);
        }
        __syncthreads();

        for (int cb = 0; cb < 16; cb += 8) {
            unsigned long long acc01[8], acc23[8];
            #pragma unroll
            for (int j = 0; j < 8; j++) {
                float bb = b2s[pass * 16 + cb + j];
                PK2(acc01[j], bb, bb);
                acc23[j] = acc01[j];
            }
            for (int ci = 0; ci < 16; ci++) {
                const float2* q0 = (const float2*)&p1s[(ci * 2 + 0) * 260 + 2 * pw];
                const float2* q1 = (const float2*)&p1s[(ci * 2 + 1) * 260 + 2 * pw];
                float2 u0 = q0[0], u1 = q0[1], u2 = q0[2];
                float2 v0 = q1[0], v1 = q1[1], v2 = q1[2];
                unsigned long long p0[5], p1p[5];
                PK2(p0[0],  u0.x, u0.y); PK2(p0[1],  u0.y, u1.x); PK2(p0[2],  u1.x, u1.y);
                PK2(p0[3],  u1.y, u2.x); PK2(p0[4],  u2.x, u2.y);
                PK2(p1p[0], v0.x, v0.y); PK2(p1p[1], v0.y, v1.x); PK2(p1p[2], v1.x, v1.y);
                PK2(p1p[3], v1.y, v2.x); PK2(p1p[4], v2.x, v2.y);
                #pragma unroll
                for (int j = 0; j < 8; j++) {
                    const unsigned long long* wd =
                        (const unsigned long long*)&wdup[((cb + j) * 240 + ci * 15) * 2];
                    if (ph == 0) {
                        #pragma unroll
                        for (int kw = 0; kw < 5; kw++) {
                            unsigned long long wA = wd[10 + kw], wB = wd[5 + kw];
                            FMA2(acc01[j], wA, p0[kw]);
                            FMA2(acc23[j], wB, p0[kw]);
                            FMA2(acc23[j], wA, p1p[kw]);
                        }
                    } else {
                        #pragma unroll
                        for (int kw = 0; kw < 5; kw++) {
                            unsigned long long wA = wd[kw], wB = wd[5 + kw];
                            FMA2(acc01[j], wA, p0[kw]);
                            FMA2(acc01[j], wB, p1p[kw]);
                            FMA2(acc23[j], wA, p1p[kw]);
                        }
                    }
                }
            }
            #pragma unroll
            for (int j = 0; j < 8; j++) {
                float a0, a1, a2, a3;
                UPK2(a0, a1, acc01[j]);
                UPK2(a2, a3, acc23[j]);
                a0 = (a0 >= 0.f) ? a0 : 0.01f * a0;
                a1 = (a1 >= 0.f) ? a1 : 0.01f * a1;
                a2 = (a2 >= 0.f) ? a2 : 0.01f * a2;
                a3 = (a3 >= 0.f) ? a3 : 0.01f * a3;
                float m  = fmaxf(fmaxf(a0, a1), fmaxf(a2, a3));
                float tv = tanhf(m);
                int fi = (pass * 16 + cb + j) * 256 + ph * 128 + pw;
                flatP[(size_t)b * FLATSZ + fi] = tv;
                o0 += tv * Wout[2 * fi];
                o1 += tv * Wout[2 * fi + 1];
            }
        }
    }

    #pragma unroll
    for (int off = 16; off > 0; off >>= 1) {
        o0 += __shfl_down_sync(0xffffffffu, o0, off);
        o1 += __shfl_down_sync(0xffffffffu, o1, off);
    }
    if ((t & 31) == 0) { redsum[t >> 5][0] = o0; redsum[t >> 5][1] = o1; }
    __syncthreads();
    if (t == 0) {
        float s0 = 0.f, s1 = 0.f;
        #pragma unroll
        for (int w = 0; w < 8; w++) { s0 += redsum[w][0]; s1 += redsum[w][1]; }
        outP[2 * b]     = s0 + bout[0];
        outP[2 * b + 1] = s1 + bout[1];
    }
}

// ---------------- launch ----------------
extern "C" void kernel_launch(void* const* d_in, const int* in_sizes, int n_in,
                              void* d_out, int out_size)
{
    (void)in_sizes; (void)n_in; (void)out_size;
    const float* r_att   = (const float*)d_in[0];
    const float* p_att   = (const float*)d_in[1];
    const float* r_fun   = (const float*)d_in[2];
    const float* p_fun   = (const float*)d_in[3];
    const int*   idx     = (const int*)  d_in[4];
    const float* W_att1  = (const float*)d_in[5];
    const float* b_att1  = (const float*)d_in[6];
    const float* W_att2  = (const float*)d_in[7];
    const float* b_att2  = (const float*)d_in[8];
    const float* W_fun1  = (const float*)d_in[9];
    const float* b_fun1  = (const float*)d_in[10];
    const float* W_fun2  = (const float*)d_in[11];
    const float* b_fun2  = (const float*)d_in[12];
    const float* conv1_w = (const float*)d_in[13];
    const float* conv1_b = (const float*)d_in[14];
    const float* conv2_w = (const float*)d_in[15];
    const float* conv2_b = (const float*)d_in[16];
    const float* W_out   = (const float*)d_in[17];
    const float* b_out   = (const float*)d_in[18];

    float* out   = (float*)d_out;
    float* e     = out;                              // [3512, 512]
    float* outP  = out + (size_t)NT * DCOLS;         // [8192, 2]
    float* flatP = outP + 2 * BATCH;                 // [8192, 8192]

    __half *Ah, *Bth, *B2h, *hiddenH;
    float  *part;
    cudaGetSymbolAddress((void**)&Ah,      g_Ah);
    cudaGetSymbolAddress((void**)&Bth,     g_Bth);
    cudaGetSymbolAddress((void**)&B2h,     g_B2h);
    cudaGetSymbolAddress((void**)&hiddenH, g_hidden_h);
    cudaGetSymbolAddress((void**)&part,    g_part);

    const int gemmSmem = NSTAGE * STG_BYTES + 16;    // 61456
    cudaFuncSetAttribute(gemm_f16, cudaFuncAttributeMaxDynamicSharedMemorySize, gemmSmem);

    const int mT = (NT + 127) / 128;                 // 28

    // ===== ATT branch =====
    {
        size_t n4 = (size_t)M_PAD * (KP_ATT / 4);
        pack_A_h<<<(unsigned)((n4 + 255) / 256), 256>>>(r_att, p_att, N_RNA, SZ_R, KP_ATT, Ah);
        convertB<<<dim3(H_ATT / 32, KP_ATT / 32), dim3(32, 8)>>>(W_att1, Bth, SZ_R, KP_ATT, H_ATT);
        gemm_f16<<<dim3(H_ATT / 128, mT, 1), 256, gemmSmem>>>(
            Ah, KP_ATT, NT, Bth, KP_ATT, H_ATT, KP_ATT, b_att1, hiddenH, nullptr, 0);
        convertB<<<dim3(256 / 32, H_ATT / 32), dim3(32, 8)>>>(W_att2, B2h, H_ATT, H_ATT, 256);
        gemm_f16<<<dim3(2, mT, SPLITS2), 256, gemmSmem>>>(
            hiddenH, H_ATT, NT, B2h, H_ATT, 256, H_ATT / SPLITS2, nullptr, nullptr, part, 1);
        gemm2_reduce<<<(NT * 256 + 255) / 256, 256>>>(part, b_att2, e, NT, 0);
    }
    // ===== FUN branch =====
    {
        size_t n4 = (size_t)M_PAD * (KP_FUN / 4);
        pack_A_h<<<(unsigned)((n4 + 255) / 256), 256>>>(r_fun, p_fun, N_RNA, FUN_IN, KP_FUN, Ah);
        convertB<<<dim3(H_FUN / 32, KP_FUN / 32), dim3(32, 8)>>>(W_fun1, Bth, FUN_IN, KP_FUN, H_FUN);
        gemm_f16<<<dim3(H_FUN / 128, mT, 1), 256, gemmSmem>>>(
            Ah, KP_FUN, NT, Bth, KP_FUN, H_FUN, KP_FUN, b_fun1, hiddenH, nullptr, 0);
        convertB<<<dim3(256 / 32, H_FUN / 32), dim3(32, 8)>>>(W_fun2, B2h, H_FUN, H_FUN, 256);
        gemm_f16<<<dim3(2, mT, SPLITS2), 256, gemmSmem>>>(
            hiddenH, H_FUN, NT, B2h, H_FUN, 256, H_FUN / SPLITS2, nullptr, nullptr, part, 1);
        gemm2_reduce<<<(NT * 256 + 255) / 256, 256>>>(part, b_fun2, e, NT, 256);
    }

    // fused conv stack — unchanged (69280 B smem, 3 CTAs/SM)
    const int convSmem = 17320 * 4;
    cudaFuncSetAttribute(conv_fused, cudaFuncAttributeMaxDynamicSharedMemorySize, convSmem);
    conv_fused<<<BATCH, 256, convSmem>>>(e, idx, conv1_w, conv1_b, conv2_w, conv2_b,
                                         W_out, b_out, outP, flatP);
}